// round 8
// baseline (speedup 1.0000x reference)
#include <cuda_runtime.h>
#include <cuda_fp16.h>
#include <cstdint>

// Shapes (fixed)
#define S  2048
#define D  512
#define KC 256

// ---------------- fp32 scratch ----------------
__device__ float g_sc[(size_t)S * S];       // scores
__device__ float g_qkv32[S * 1024];         // packed q|k|v fp32 (blocks 2/3)
__device__ float g_h2[S * D];               // block-2 output fp32
__device__ float g_qrow[KC];
__device__ float g_srow[S];

// ---------------- fp16 hi/lo scratch (16B aligned) ----------------
#define HBUF(name, n) __device__ __align__(16) __half name[n]
HBUF(g_xh,  S * D);   HBUF(g_xl,  S * D);
HBUF(g_xTh, D * S);   HBUF(g_xTl, D * S);
HBUF(g_wqk1h, 512 * D);  HBUF(g_wqk1l, 512 * D);     // [Wq1;Wk1] K-major
HBUF(g_wqkv2h, 1024 * D); HBUF(g_wqkv2l, 1024 * D);  // [Wq2;Wk2;Wv2] K-major
HBUF(g_qk1h, S * 512);  HBUF(g_qk1l, S * 512);
HBUF(g_qkvh, S * 1024); HBUF(g_qkvl, S * 1024);
HBUF(g_ph, (size_t)S * S);  HBUF(g_pl, (size_t)S * S);
HBUF(g_h1h, S * D);  HBUF(g_h1l, S * D);
HBUF(g_vTh, D * S);  HBUF(g_vTl, D * S);
HBUF(g_h2h, S * D);  HBUF(g_h2l, S * D);

// ---------------- helpers ----------------
__device__ __forceinline__ uint32_t smem_u32(const void* p) {
    uint32_t a;
    asm("{ .reg .u64 t; cvta.to.shared.u64 t, %1; cvt.u32.u64 %0, t; }" : "=r"(a) : "l"(p));
    return a;
}
__device__ __forceinline__ void ldsm4(uint32_t* r, uint32_t a) {
    asm volatile("ldmatrix.sync.aligned.m8n8.x4.shared.b16 {%0,%1,%2,%3}, [%4];"
                 : "=r"(r[0]), "=r"(r[1]), "=r"(r[2]), "=r"(r[3]) : "r"(a));
}
__device__ __forceinline__ void mma_f16(float* c, const uint32_t* a, const uint32_t* b) {
    asm volatile(
        "mma.sync.aligned.m16n8k16.row.col.f32.f16.f16.f32 "
        "{%0,%1,%2,%3}, {%4,%5,%6,%7}, {%8,%9}, {%0,%1,%2,%3};"
        : "+f"(c[0]), "+f"(c[1]), "+f"(c[2]), "+f"(c[3])
        : "r"(a[0]), "r"(a[1]), "r"(a[2]), "r"(a[3]), "r"(b[0]), "r"(b[1]));
}
__device__ __forceinline__ void cp16(uint32_t dst, const void* src) {
    asm volatile("cp.async.cg.shared.global [%0], [%1], 16;" :: "r"(dst), "l"(src));
}
#define CP_COMMIT() asm volatile("cp.async.commit_group;" ::: "memory")
#define CP_WAIT1()  asm volatile("cp.async.wait_group 1;" ::: "memory")

__device__ __forceinline__ void split1(float v, __half& h, __half& l) {
    h = __float2half_rn(v);
    l = __float2half_rn(v - __half2float(h));
}

// ---------------- fp16 hi/lo split tensor-core GEMM ----------------
// C[M,N] = (Ah+Al)[M,K] * (Bh+Bl)[N,K]^T + bias.  K-major fp16 operands.
// OUT: 0 = fp32 C; 1 = fp16 Ch/Cl; 2 = both.
// BMODE: 0 none; 1 two-way bias split at col 256; 2 three-way at 256/512.
// OCC: min CTAs/SM for launch_bounds.
#define ROWB 80

template <int BM, int BN, int WM, int WN, int OUT, int BMODE, int OCC>
__global__ void __launch_bounds__(WM* WN * 32, OCC) mma_gemm(
    const __half* __restrict__ Ah, const __half* __restrict__ Al,
    const __half* __restrict__ Bh, const __half* __restrict__ Bl,
    const float* __restrict__ Bi0, const float* __restrict__ Bi1,
    const float* __restrict__ Bi2,
    float* __restrict__ C, __half* __restrict__ Ch, __half* __restrict__ Cl,
    int K, int lda, int ldb, int ldc)
{
    constexpr int T = WM * WN * 32;
    constexpr int WTM = BM / WM, WTN = BN / WN;
    constexpr int MT = WTM / 16, NT = WTN / 8;
    constexpr int ATILE = BM * ROWB;
    constexpr int BTILE = BN * ROWB;
    constexpr int STAGE = 2 * ATILE + 2 * BTILE;

    extern __shared__ char smc[];
    const uint32_t sb0 = smem_u32(smc);
    const int t = threadIdx.x, lane = t & 31, wid = t >> 5;
    const int wm = (wid % WM) * WTM, wn = (wid / WM) * WTN;
    const int m0 = blockIdx.y * BM, n0 = blockIdx.x * BN;

    float acc[MT][NT][4];
    #pragma unroll
    for (int i = 0; i < MT; i++)
        #pragma unroll
        for (int j = 0; j < NT; j++)
            #pragma unroll
            for (int k = 0; k < 4; k++) acc[i][j][k] = 0.f;

    const int NC = K >> 5;

    auto cp_chunk = [&](uint32_t st, int k0) {
        #pragma unroll
        for (int i = 0; i < (BM * 4) / T; i++) {
            int v = t + i * T; int r = v >> 2, s = v & 3;
            uint32_t d = st + (uint32_t)(r * ROWB + s * 16);
            const size_t o = (size_t)(m0 + r) * lda + k0 + s * 8;
            cp16(d, Ah + o);
            cp16(d + ATILE, Al + o);
        }
        #pragma unroll
        for (int i = 0; i < (BN * 4) / T; i++) {
            int v = t + i * T; int r = v >> 2, s = v & 3;
            uint32_t d = st + 2 * ATILE + (uint32_t)(r * ROWB + s * 16);
            const size_t o = (size_t)(n0 + r) * ldb + k0 + s * 8;
            cp16(d, Bh + o);
            cp16(d + BTILE, Bl + o);
        }
    };

    auto mma_stage = [&](uint32_t st) {
        const int l7 = lane & 7, mt = lane >> 3;
        #pragma unroll
        for (int ks = 0; ks < 2; ks++) {
            uint32_t af_h[MT][4], af_l[MT][4];
            #pragma unroll
            for (int mi = 0; mi < MT; mi++) {
                uint32_t ra = st + (uint32_t)((wm + mi * 16 + l7 + ((mt & 1) << 3)) * ROWB
                                              + ks * 32 + ((mt >> 1) << 4));
                ldsm4(af_h[mi], ra);
                ldsm4(af_l[mi], ra + ATILE);
            }
            uint32_t bf_h[NT][2], bf_l[NT][2];
            #pragma unroll
            for (int np = 0; np < NT / 2; np++) {
                uint32_t rb = st + 2 * ATILE
                            + (uint32_t)((wn + np * 16 + ((mt >> 1) << 3) + l7) * ROWB
                                         + ks * 32 + ((mt & 1) << 4));
                uint32_t r4[4];
                ldsm4(r4, rb);
                bf_h[2 * np][0] = r4[0]; bf_h[2 * np][1] = r4[1];
                bf_h[2 * np + 1][0] = r4[2]; bf_h[2 * np + 1][1] = r4[3];
                ldsm4(r4, rb + BTILE);
                bf_l[2 * np][0] = r4[0]; bf_l[2 * np][1] = r4[1];
                bf_l[2 * np + 1][0] = r4[2]; bf_l[2 * np + 1][1] = r4[3];
            }
            #pragma unroll
            for (int mi = 0; mi < MT; mi++)
                #pragma unroll
                for (int ni = 0; ni < NT; ni++) {
                    mma_f16(acc[mi][ni], af_h[mi], bf_h[ni]);
                    mma_f16(acc[mi][ni], af_h[mi], bf_l[ni]);
                    mma_f16(acc[mi][ni], af_l[mi], bf_h[ni]);
                }
        }
    };

    cp_chunk(sb0, 0);
    CP_COMMIT();
    if (NC > 1) cp_chunk(sb0 + STAGE, 32);
    CP_COMMIT();
    for (int c = 0; c < NC; c++) {
        CP_WAIT1();
        __syncthreads();
        mma_stage(sb0 + (uint32_t)((c % 3) * STAGE));
        // cp(c+2) writes buffer (c-1)%3 whose readers passed the barrier above.
        if (c + 2 < NC) cp_chunk(sb0 + (uint32_t)(((c + 2) % 3) * STAGE), (c + 2) * 32);
        CP_COMMIT();
    }

    // epilogue
    const int g = lane >> 2, w2 = (lane & 3) * 2;
    #pragma unroll
    for (int ni = 0; ni < NT; ni++) {
        const int col = n0 + wn + ni * 8 + w2;
        float b0v = 0.f, b1v = 0.f;
        if (BMODE == 1) {
            const float* bp = (col < 256) ? Bi0 : (Bi1 - 256);
            b0v = bp[col]; b1v = bp[col + 1];
        } else if (BMODE == 2) {
            const float* bp = (col < 256) ? Bi0 : (col < 512 ? (Bi1 - 256) : (Bi2 - 512));
            b0v = bp[col]; b1v = bp[col + 1];
        }
        #pragma unroll
        for (int mi = 0; mi < MT; mi++) {
            const int row = m0 + wm + mi * 16 + g;
            float c00 = acc[mi][ni][0] + b0v, c01 = acc[mi][ni][1] + b1v;
            float c10 = acc[mi][ni][2] + b0v, c11 = acc[mi][ni][3] + b1v;
            if (OUT == 0 || OUT == 2) {
                *reinterpret_cast<float2*>(&C[(size_t)row * ldc + col]) = make_float2(c00, c01);
                *reinterpret_cast<float2*>(&C[(size_t)(row + 8) * ldc + col]) = make_float2(c10, c11);
            }
            if (OUT >= 1) {
                __half h0, l0, h1, l1;
                split1(c00, h0, l0); split1(c01, h1, l1);
                *reinterpret_cast<__half2*>(&Ch[(size_t)row * ldc + col]) = __halves2half2(h0, h1);
                *reinterpret_cast<__half2*>(&Cl[(size_t)row * ldc + col]) = __halves2half2(l0, l1);
                split1(c10, h0, l0); split1(c11, h1, l1);
                *reinterpret_cast<__half2*>(&Ch[(size_t)(row + 8) * ldc + col]) = __halves2half2(h0, h1);
                *reinterpret_cast<__half2*>(&Cl[(size_t)(row + 8) * ldc + col]) = __halves2half2(l0, l1);
            }
        }
    }
}

// proj/AV config: 128x64 tile, 256 threads (WM=4, WN=2), 2 CTAs/SM
#define SMEMP  (3 * (2 * 128 * ROWB + 2 * 64 * ROWB))      // 92160
// scores config: 128x128 tile, 512 threads (WM=4, WN=4), 1 CTA/SM
#define SMEMS  (3 * (2 * 128 * ROWB + 2 * 128 * ROWB))     // 122880

// ---------------- converts ----------------
template <bool STRAIGHT>
__global__ void cvt_split_T(const float* __restrict__ in, int ldin,
                            __half* __restrict__ oh, __half* __restrict__ ol,
                            __half* __restrict__ sh, __half* __restrict__ sl,
                            int R, int C)
{
    __shared__ float tile[32][33];
    const int c0 = blockIdx.x * 32, r0 = blockIdx.y * 32;
    const int tx = threadIdx.x, ty = threadIdx.y;
    #pragma unroll
    for (int i = 0; i < 32; i += 8) {
        float v = in[(size_t)(r0 + ty + i) * ldin + c0 + tx];
        tile[ty + i][tx] = v;
        if (STRAIGHT) {
            __half h, l;
            split1(v, h, l);
            const size_t o = (size_t)(r0 + ty + i) * C + c0 + tx;
            sh[o] = h;
            sl[o] = l;
        }
    }
    __syncthreads();
    #pragma unroll
    for (int i = 0; i < 32; i += 8) {
        float v = tile[tx][ty + i];
        __half h, l;
        split1(v, h, l);
        const size_t o = (size_t)(c0 + ty + i) * R + r0 + tx;
        oh[o] = h;
        ol[o] = l;
    }
}

__global__ void cvt_T_pair(const float* __restrict__ A, const float* __restrict__ B,
                           __half* __restrict__ oh, __half* __restrict__ ol,
                           int R, int C)
{
    __shared__ float tile[32][33];
    const int z = blockIdx.z;
    const float* in = z ? B : A;
    const size_t zoff = (size_t)z * C * R;
    const int c0 = blockIdx.x * 32, r0 = blockIdx.y * 32;
    const int tx = threadIdx.x, ty = threadIdx.y;
    #pragma unroll
    for (int i = 0; i < 32; i += 8)
        tile[ty + i][tx] = in[(size_t)(r0 + ty + i) * C + c0 + tx];
    __syncthreads();
    #pragma unroll
    for (int i = 0; i < 32; i += 8) {
        float v = tile[tx][ty + i];
        __half h, l;
        split1(v, h, l);
        const size_t o = zoff + (size_t)(c0 + ty + i) * R + r0 + tx;
        oh[o] = h;
        ol[o] = l;
    }
}

// ---------------- register-resident softmax + fp16 split output ----------------
__global__ void softmax_cvt(const float* __restrict__ Sc, __half* __restrict__ Ph,
                            __half* __restrict__ Pl)
{
    const size_t base = (size_t)blockIdx.x * S;
    const int t = threadIdx.x, lane = t & 31, wid = t >> 5;
    __shared__ float red[8];

    float4 v0 = *reinterpret_cast<const float4*>(Sc + base + t * 4);
    float4 v1 = *reinterpret_cast<const float4*>(Sc + base + 1024 + t * 4);
    float m = fmaxf(fmaxf(fmaxf(v0.x, v0.y), fmaxf(v0.z, v0.w)),
                    fmaxf(fmaxf(v1.x, v1.y), fmaxf(v1.z, v1.w)));
    #pragma unroll
    for (int o = 16; o > 0; o >>= 1) m = fmaxf(m, __shfl_xor_sync(0xffffffffu, m, o));
    if (lane == 0) red[wid] = m;
    __syncthreads();
    m = red[0];
    #pragma unroll
    for (int i = 1; i < 8; i++) m = fmaxf(m, red[i]);
    __syncthreads();

    float e[8];
    e[0] = __expf(v0.x - m); e[1] = __expf(v0.y - m);
    e[2] = __expf(v0.z - m); e[3] = __expf(v0.w - m);
    e[4] = __expf(v1.x - m); e[5] = __expf(v1.y - m);
    e[6] = __expf(v1.z - m); e[7] = __expf(v1.w - m);
    float s = e[0] + e[1] + e[2] + e[3] + e[4] + e[5] + e[6] + e[7];
    #pragma unroll
    for (int o = 16; o > 0; o >>= 1) s += __shfl_xor_sync(0xffffffffu, s, o);
    if (lane == 0) red[wid] = s;
    __syncthreads();
    s = red[0];
    #pragma unroll
    for (int i = 1; i < 8; i++) s += red[i];
    const float inv = 1.0f / s;

    #pragma unroll
    for (int half = 0; half < 2; half++) {
        const size_t o = base + half * 1024 + t * 4;
        __half h0, l0, h1, l1, h2, l2, h3, l3;
        split1(e[half * 4 + 0] * inv, h0, l0);
        split1(e[half * 4 + 1] * inv, h1, l1);
        split1(e[half * 4 + 2] * inv, h2, l2);
        split1(e[half * 4 + 3] * inv, h3, l3);
        *reinterpret_cast<__half2*>(Ph + o)     = __halves2half2(h0, h1);
        *reinterpret_cast<__half2*>(Ph + o + 2) = __halves2half2(h2, h3);
        *reinterpret_cast<__half2*>(Pl + o)     = __halves2half2(l0, l1);
        *reinterpret_cast<__half2*>(Pl + o + 2) = __halves2half2(l2, l3);
    }
}

// ---------------- row-wise L2 normalize (strided) ----------------
__global__ void l2norm_rows(float* __restrict__ V, int ld, int cols)
{
    float* row = V + (size_t)blockIdx.x * ld;
    __shared__ float red[128];
    const int t = threadIdx.x;
    float s = 0.f;
    for (int c = t; c < cols; c += 128) { float v = row[c]; s += v * v; }
    red[t] = s; __syncthreads();
    for (int st = 64; st > 0; st >>= 1) { if (t < st) red[t] += red[t + st]; __syncthreads(); }
    const float inv = 1.0f / sqrtf(red[0]);
    for (int c = t; c < cols; c += 128) row[c] *= inv;
}

// ---------------- block-3 tail ----------------
__global__ void rowproj(const float* __restrict__ h, const float* __restrict__ W,
                        const float* __restrict__ b, float* __restrict__ out,
                        int Din, int Nout)
{
    const int n = threadIdx.x;
    if (n >= Nout) return;
    float s = b[n];
    for (int d = 0; d < Din; d++) s = fmaf(h[d], W[(size_t)d * Nout + n], s);
    out[n] = s;
}

__global__ void dotrow(const float* __restrict__ q, const float* __restrict__ Kmat,
                       int ld, float* __restrict__ srow, int Kd)
{
    const int j = blockIdx.x;
    const int t = threadIdx.x;
    float s = 0.f;
    for (int c = t; c < Kd; c += 32) s = fmaf(q[c], Kmat[(size_t)j * ld + c], s);
    #pragma unroll
    for (int o = 16; o > 0; o >>= 1) s += __shfl_down_sync(0xffffffffu, s, o);
    if (t == 0) srow[j] = s;
}

__global__ void zero_out(float* out) { out[threadIdx.x + blockIdx.x * 256] = 0.f; }

// fused softmax (redundant per block) + slice-AV with atomic reduce
__global__ void av_split(const float* __restrict__ srow, const float* __restrict__ V,
                         int ld, float* __restrict__ out)
{
    __shared__ float probs[S];
    __shared__ float red[8];
    const int t = threadIdx.x, lane = t & 31, wid = t >> 5;

    float v[8];
    #pragma unroll
    for (int i = 0; i < 8; i++) v[i] = srow[t + i * 256];
    float m = v[0];
    #pragma unroll
    for (int i = 1; i < 8; i++) m = fmaxf(m, v[i]);
    #pragma unroll
    for (int o = 16; o > 0; o >>= 1) m = fmaxf(m, __shfl_xor_sync(0xffffffffu, m, o));
    if (lane == 0) red[wid] = m;
    __syncthreads();
    m = red[0];
    #pragma unroll
    for (int i = 1; i < 8; i++) m = fmaxf(m, red[i]);
    __syncthreads();

    float s = 0.f;
    #pragma unroll
    for (int i = 0; i < 8; i++) {
        float e = __expf(v[i] - m);
        probs[t + i * 256] = e;
        s += e;
    }
    #pragma unroll
    for (int o = 16; o > 0; o >>= 1) s += __shfl_xor_sync(0xffffffffu, s, o);
    if (lane == 0) red[wid] = s;
    __syncthreads();
    s = red[0];
    #pragma unroll
    for (int i = 1; i < 8; i++) s += red[i];
    const float inv = 1.0f / s;
    __syncthreads();

    const int d = blockIdx.x * 256 + t;
    const int j0 = blockIdx.y * 128;
    float acc = 0.f;
    #pragma unroll 4
    for (int j = j0; j < j0 + 128; j++)
        acc = fmaf(probs[j], V[(size_t)j * ld + d], acc);
    atomicAdd(out + d, acc * inv);
}

// ---------------- launch ----------------
extern "C" void kernel_launch(void* const* d_in, const int* in_sizes, int n_in,
                              void* d_out, int out_size)
{
    const float* x   = (const float*)d_in[0];   // [8,S,D] — batch 0 only
    const float* Wk1 = (const float*)d_in[1];
    const float* bk1 = (const float*)d_in[2];
    const float* Wq1 = (const float*)d_in[3];
    const float* bq1 = (const float*)d_in[4];
    const float* Wk2 = (const float*)d_in[5];
    const float* bk2 = (const float*)d_in[6];
    const float* Wq2 = (const float*)d_in[7];
    const float* bq2 = (const float*)d_in[8];
    const float* Wv2 = (const float*)d_in[9];
    const float* bv2 = (const float*)d_in[10];
    float* out = (float*)d_out;

    float *sc, *qkv32, *h2, *qrow, *srow;
    cudaGetSymbolAddress((void**)&sc,    g_sc);
    cudaGetSymbolAddress((void**)&qkv32, g_qkv32);
    cudaGetSymbolAddress((void**)&h2,    g_h2);
    cudaGetSymbolAddress((void**)&qrow,  g_qrow);
    cudaGetSymbolAddress((void**)&srow,  g_srow);

    __half *xh, *xl, *xTh, *xTl, *wqk1h, *wqk1l, *wqkv2h, *wqkv2l;
    __half *qk1h, *qk1l, *qkvh, *qkvl, *ph, *pl, *h1h, *h1l, *vTh, *vTl, *h2h, *h2l;
    cudaGetSymbolAddress((void**)&xh, g_xh);   cudaGetSymbolAddress((void**)&xl, g_xl);
    cudaGetSymbolAddress((void**)&xTh, g_xTh); cudaGetSymbolAddress((void**)&xTl, g_xTl);
    cudaGetSymbolAddress((void**)&wqk1h, g_wqk1h);   cudaGetSymbolAddress((void**)&wqk1l, g_wqk1l);
    cudaGetSymbolAddress((void**)&wqkv2h, g_wqkv2h); cudaGetSymbolAddress((void**)&wqkv2l, g_wqkv2l);
    cudaGetSymbolAddress((void**)&qk1h, g_qk1h); cudaGetSymbolAddress((void**)&qk1l, g_qk1l);
    cudaGetSymbolAddress((void**)&qkvh, g_qkvh); cudaGetSymbolAddress((void**)&qkvl, g_qkvl);
    cudaGetSymbolAddress((void**)&ph, g_ph); cudaGetSymbolAddress((void**)&pl, g_pl);
    cudaGetSymbolAddress((void**)&h1h, g_h1h); cudaGetSymbolAddress((void**)&h1l, g_h1l);
    cudaGetSymbolAddress((void**)&vTh, g_vTh); cudaGetSymbolAddress((void**)&vTl, g_vTl);
    cudaGetSymbolAddress((void**)&h2h, g_h2h); cudaGetSymbolAddress((void**)&h2l, g_h2l);

    cudaFuncSetAttribute((const void*)mma_gemm<128, 64, 4, 2, 1, 1, 2>,
                         cudaFuncAttributeMaxDynamicSharedMemorySize, SMEMP);
    cudaFuncSetAttribute((const void*)mma_gemm<128, 64, 4, 2, 1, 0, 2>,
                         cudaFuncAttributeMaxDynamicSharedMemorySize, SMEMP);
    cudaFuncSetAttribute((const void*)mma_gemm<128, 64, 4, 2, 2, 2, 2>,
                         cudaFuncAttributeMaxDynamicSharedMemorySize, SMEMP);
    cudaFuncSetAttribute((const void*)mma_gemm<128, 64, 4, 2, 2, 0, 2>,
                         cudaFuncAttributeMaxDynamicSharedMemorySize, SMEMP);
    cudaFuncSetAttribute((const void*)mma_gemm<128, 64, 4, 2, 0, 2, 2>,
                         cudaFuncAttributeMaxDynamicSharedMemorySize, SMEMP);
    cudaFuncSetAttribute((const void*)mma_gemm<128, 128, 4, 4, 0, 0, 1>,
                         cudaFuncAttributeMaxDynamicSharedMemorySize, SMEMS);

    const dim3 gP1(512 / 64, S / 128);    // (8,16)
    const dim3 gP2(1024 / 64, S / 128);   // (16,16)
    const dim3 gScor(S / 128, S / 128);   // (16,16)
    const dim3 gAV(D / 64, S / 128);      // (8,16)
    const dim3 tT(32, 8);

    // ---------- Block 1 ----------
    cvt_split_T<true><<<dim3(D / 32, S / 32), tT>>>(x, D, xTh, xTl, xh, xl, S, D);
    cvt_T_pair<<<dim3(KC / 32, D / 32, 2), tT>>>(Wq1, Wk1, wqk1h, wqk1l, D, KC);
    mma_gemm<128, 64, 4, 2, 1, 1, 2><<<gP1, 256, SMEMP>>>(xh, xl, wqk1h, wqk1l,
        bq1, bk1, nullptr, nullptr, qk1h, qk1l, D, D, D, 512);
    mma_gemm<128, 128, 4, 4, 0, 0, 1><<<gScor, 512, SMEMS>>>(qk1h, qk1l, qk1h + 256, qk1l + 256,
        nullptr, nullptr, nullptr, sc, nullptr, nullptr, KC, 512, 512, S);
    softmax_cvt<<<S, 256>>>(sc, ph, pl);
    mma_gemm<128, 64, 4, 2, 1, 0, 2><<<gAV, 256, SMEMP>>>(ph, pl, xTh, xTl,
        nullptr, nullptr, nullptr, nullptr, h1h, h1l, S, S, S, D);

    // ---------- Block 2 ----------
    cvt_T_pair<<<dim3(KC / 32, D / 32, 2), tT>>>(Wq2, Wk2, wqkv2h, wqkv2l, D, KC);
    cvt_split_T<false><<<dim3(D / 32, D / 32), tT>>>(Wv2, D, wqkv2h + 512 * D, wqkv2l + 512 * D,
        nullptr, nullptr, D, D);
    mma_gemm<128, 64, 4, 2, 2, 2, 2><<<gP2, 256, SMEMP>>>(h1h, h1l, wqkv2h, wqkv2l,
        bq2, bk2, bv2, qkv32, qkvh, qkvl, D, D, D, 1024);
    l2norm_rows<<<S, 128>>>(qkv32 + 512, 1024, D);
    cvt_split_T<false><<<dim3(D / 32, S / 32), tT>>>(qkv32 + 512, 1024, vTh, vTl,
        nullptr, nullptr, S, D);
    mma_gemm<128, 128, 4, 4, 0, 0, 1><<<gScor, 512, SMEMS>>>(qkvh, qkvl, qkvh + 256, qkvl + 256,
        nullptr, nullptr, nullptr, sc, nullptr, nullptr, KC, 1024, 1024, S);
    softmax_cvt<<<S, 256>>>(sc, ph, pl);
    mma_gemm<128, 64, 4, 2, 2, 0, 2><<<gAV, 256, SMEMP>>>(ph, pl, vTh, vTl,
        nullptr, nullptr, nullptr, h2, h2h, h2l, S, S, S, D);

    // ---------- Block 3 (only last query row needed) ----------
    mma_gemm<128, 64, 4, 2, 0, 2, 2><<<gP2, 256, SMEMP>>>(h2h, h2l, wqkv2h, wqkv2l,
        bq2, bk2, bv2, qkv32, nullptr, nullptr, D, D, D, 1024);
    l2norm_rows<<<S, 128>>>(qkv32 + 512, 1024, D);
    rowproj<<<1, KC>>>(h2 + (size_t)(S - 1) * D, Wq2, bq2, qrow, D, KC);
    dotrow<<<S, 32>>>(qrow, qkv32 + 256, 1024, srow, KC);
    zero_out<<<2, 256>>>(out);
    av_split<<<dim3(2, 16), 256>>>(srow, qkv32 + 512, 1024, out);
}

// round 10
// speedup vs baseline: 1.0356x; 1.0356x over previous
#include <cuda_runtime.h>
#include <cuda_fp16.h>
#include <cstdint>

// Shapes (fixed)
#define S  2048
#define D  512
#define KC 256

// ---------------- fp32 scratch ----------------
__device__ float g_sc[(size_t)S * S];       // scores
__device__ float g_qkv32[S * 1024];         // packed q|k|v fp32 (blocks 2/3)
__device__ float g_h2[S * D];               // block-2 output fp32
__device__ float g_qrow[KC];
__device__ float g_srow[S];

// ---------------- fp16 hi/lo scratch (16B aligned) ----------------
#define HBUF(name, n) __device__ __align__(16) __half name[n]
HBUF(g_xh,  S * D);   HBUF(g_xl,  S * D);
HBUF(g_xTh, D * S);   HBUF(g_xTl, D * S);
HBUF(g_wqk1h, 512 * D);  HBUF(g_wqk1l, 512 * D);     // [Wq1;Wk1] K-major
HBUF(g_wqkv2h, 1024 * D); HBUF(g_wqkv2l, 1024 * D);  // [Wq2;Wk2;Wv2] K-major
HBUF(g_qk1h, S * 512);  HBUF(g_qk1l, S * 512);
HBUF(g_qkvh, S * 1024); HBUF(g_qkvl, S * 1024);
HBUF(g_ph, (size_t)S * S);  HBUF(g_pl, (size_t)S * S);
HBUF(g_h1h, S * D);  HBUF(g_h1l, S * D);
HBUF(g_vTh, D * S);  HBUF(g_vTl, D * S);
HBUF(g_h2h, S * D);  HBUF(g_h2l, S * D);

// ---------------- helpers ----------------
__device__ __forceinline__ uint32_t smem_u32(const void* p) {
    uint32_t a;
    asm("{ .reg .u64 t; cvta.to.shared.u64 t, %1; cvt.u32.u64 %0, t; }" : "=r"(a) : "l"(p));
    return a;
}
__device__ __forceinline__ void ldsm4(uint32_t* r, uint32_t a) {
    asm volatile("ldmatrix.sync.aligned.m8n8.x4.shared.b16 {%0,%1,%2,%3}, [%4];"
                 : "=r"(r[0]), "=r"(r[1]), "=r"(r[2]), "=r"(r[3]) : "r"(a));
}
__device__ __forceinline__ void mma_f16(float* c, const uint32_t* a, const uint32_t* b) {
    asm volatile(
        "mma.sync.aligned.m16n8k16.row.col.f32.f16.f16.f32 "
        "{%0,%1,%2,%3}, {%4,%5,%6,%7}, {%8,%9}, {%0,%1,%2,%3};"
        : "+f"(c[0]), "+f"(c[1]), "+f"(c[2]), "+f"(c[3])
        : "r"(a[0]), "r"(a[1]), "r"(a[2]), "r"(a[3]), "r"(b[0]), "r"(b[1]));
}
__device__ __forceinline__ void cp16(uint32_t dst, const void* src) {
    asm volatile("cp.async.cg.shared.global [%0], [%1], 16;" :: "r"(dst), "l"(src));
}
#define CP_COMMIT() asm volatile("cp.async.commit_group;" ::: "memory")
#define CP_WAIT1()  asm volatile("cp.async.wait_group 1;" ::: "memory")

__device__ __forceinline__ void split1(float v, __half& h, __half& l) {
    h = __float2half_rn(v);
    l = __float2half_rn(v - __half2float(h));
}

// ---------------- fp16 hi/lo split tensor-core GEMM ----------------
// C[M,N] = (Ah+Al)[M,K] * (Bh+Bl)[N,K]^T + bias.  K-major fp16 operands.
// OUT: 0 = fp32 C; 1 = fp16 Ch/Cl; 2 = both.
// BMODE: 0 none; 1 two-way bias split at col 256; 2 three-way at 256/512.
// OCC: min CTAs/SM for launch_bounds.
#define ROWB 80

template <int BM, int BN, int WM, int WN, int OUT, int BMODE, int OCC>
__global__ void __launch_bounds__(WM* WN * 32, OCC) mma_gemm(
    const __half* __restrict__ Ah, const __half* __restrict__ Al,
    const __half* __restrict__ Bh, const __half* __restrict__ Bl,
    const float* __restrict__ Bi0, const float* __restrict__ Bi1,
    const float* __restrict__ Bi2,
    float* __restrict__ C, __half* __restrict__ Ch, __half* __restrict__ Cl,
    int K, int lda, int ldb, int ldc)
{
    constexpr int T = WM * WN * 32;
    constexpr int WTM = BM / WM, WTN = BN / WN;
    constexpr int MT = WTM / 16, NT = WTN / 8;
    constexpr int ATILE = BM * ROWB;
    constexpr int BTILE = BN * ROWB;
    constexpr int STAGE = 2 * ATILE + 2 * BTILE;

    extern __shared__ char smc[];
    const uint32_t sb0 = smem_u32(smc);
    const int t = threadIdx.x, lane = t & 31, wid = t >> 5;
    const int wm = (wid % WM) * WTM, wn = (wid / WM) * WTN;
    const int m0 = blockIdx.y * BM, n0 = blockIdx.x * BN;

    float acc[MT][NT][4];
    #pragma unroll
    for (int i = 0; i < MT; i++)
        #pragma unroll
        for (int j = 0; j < NT; j++)
            #pragma unroll
            for (int k = 0; k < 4; k++) acc[i][j][k] = 0.f;

    const int NC = K >> 5;

    auto cp_chunk = [&](uint32_t st, int k0) {
        #pragma unroll
        for (int i = 0; i < (BM * 4) / T; i++) {
            int v = t + i * T; int r = v >> 2, s = v & 3;
            uint32_t d = st + (uint32_t)(r * ROWB + s * 16);
            const size_t o = (size_t)(m0 + r) * lda + k0 + s * 8;
            cp16(d, Ah + o);
            cp16(d + ATILE, Al + o);
        }
        #pragma unroll
        for (int i = 0; i < (BN * 4) / T; i++) {
            int v = t + i * T; int r = v >> 2, s = v & 3;
            uint32_t d = st + 2 * ATILE + (uint32_t)(r * ROWB + s * 16);
            const size_t o = (size_t)(n0 + r) * ldb + k0 + s * 8;
            cp16(d, Bh + o);
            cp16(d + BTILE, Bl + o);
        }
    };

    auto mma_stage = [&](uint32_t st) {
        const int l7 = lane & 7, mt = lane >> 3;
        #pragma unroll
        for (int ks = 0; ks < 2; ks++) {
            uint32_t af_h[MT][4], af_l[MT][4];
            #pragma unroll
            for (int mi = 0; mi < MT; mi++) {
                uint32_t ra = st + (uint32_t)((wm + mi * 16 + l7 + ((mt & 1) << 3)) * ROWB
                                              + ks * 32 + ((mt >> 1) << 4));
                ldsm4(af_h[mi], ra);
                ldsm4(af_l[mi], ra + ATILE);
            }
            uint32_t bf_h[NT][2], bf_l[NT][2];
            #pragma unroll
            for (int np = 0; np < NT / 2; np++) {
                uint32_t rb = st + 2 * ATILE
                            + (uint32_t)((wn + np * 16 + ((mt >> 1) << 3) + l7) * ROWB
                                         + ks * 32 + ((mt & 1) << 4));
                uint32_t r4[4];
                ldsm4(r4, rb);
                bf_h[2 * np][0] = r4[0]; bf_h[2 * np][1] = r4[1];
                bf_h[2 * np + 1][0] = r4[2]; bf_h[2 * np + 1][1] = r4[3];
                ldsm4(r4, rb + BTILE);
                bf_l[2 * np][0] = r4[0]; bf_l[2 * np][1] = r4[1];
                bf_l[2 * np + 1][0] = r4[2]; bf_l[2 * np + 1][1] = r4[3];
            }
            #pragma unroll
            for (int mi = 0; mi < MT; mi++)
                #pragma unroll
                for (int ni = 0; ni < NT; ni++) {
                    mma_f16(acc[mi][ni], af_h[mi], bf_h[ni]);
                    mma_f16(acc[mi][ni], af_h[mi], bf_l[ni]);
                    mma_f16(acc[mi][ni], af_l[mi], bf_h[ni]);
                }
        }
    };

    cp_chunk(sb0, 0);
    CP_COMMIT();
    if (NC > 1) cp_chunk(sb0 + STAGE, 32);
    CP_COMMIT();
    for (int c = 0; c < NC; c++) {
        CP_WAIT1();
        __syncthreads();
        mma_stage(sb0 + (uint32_t)((c % 3) * STAGE));
        // cp(c+2) writes buffer (c-1)%3 whose readers passed the barrier above.
        if (c + 2 < NC) cp_chunk(sb0 + (uint32_t)(((c + 2) % 3) * STAGE), (c + 2) * 32);
        CP_COMMIT();
    }

    // epilogue
    const int g = lane >> 2, w2 = (lane & 3) * 2;
    #pragma unroll
    for (int ni = 0; ni < NT; ni++) {
        const int col = n0 + wn + ni * 8 + w2;
        float b0v = 0.f, b1v = 0.f;
        if (BMODE == 1) {
            const float* bp = (col < 256) ? Bi0 : (Bi1 - 256);
            b0v = bp[col]; b1v = bp[col + 1];
        } else if (BMODE == 2) {
            const float* bp = (col < 256) ? Bi0 : (col < 512 ? (Bi1 - 256) : (Bi2 - 512));
            b0v = bp[col]; b1v = bp[col + 1];
        }
        #pragma unroll
        for (int mi = 0; mi < MT; mi++) {
            const int row = m0 + wm + mi * 16 + g;
            float c00 = acc[mi][ni][0] + b0v, c01 = acc[mi][ni][1] + b1v;
            float c10 = acc[mi][ni][2] + b0v, c11 = acc[mi][ni][3] + b1v;
            if (OUT == 0 || OUT == 2) {
                *reinterpret_cast<float2*>(&C[(size_t)row * ldc + col]) = make_float2(c00, c01);
                *reinterpret_cast<float2*>(&C[(size_t)(row + 8) * ldc + col]) = make_float2(c10, c11);
            }
            if (OUT >= 1) {
                __half h0, l0, h1, l1;
                split1(c00, h0, l0); split1(c01, h1, l1);
                *reinterpret_cast<__half2*>(&Ch[(size_t)row * ldc + col]) = __halves2half2(h0, h1);
                *reinterpret_cast<__half2*>(&Cl[(size_t)row * ldc + col]) = __halves2half2(l0, l1);
                split1(c10, h0, l0); split1(c11, h1, l1);
                *reinterpret_cast<__half2*>(&Ch[(size_t)(row + 8) * ldc + col]) = __halves2half2(h0, h1);
                *reinterpret_cast<__half2*>(&Cl[(size_t)(row + 8) * ldc + col]) = __halves2half2(l0, l1);
            }
        }
    }
}

// proj/AV config: 128x64 tile, 128 threads (4 warps, warp 64x32), 2 CTAs/SM, 3-stage
#define SMEMP  (3 * (2 * 128 * ROWB + 2 * 64 * ROWB))       // 92160
// scores config: 256x128 tile, 256 threads (8 warps, warp 64x64), 1 CTA/SM, 3-stage
#define SMEMS  (3 * (2 * 256 * ROWB + 2 * 128 * ROWB))      // 184320

// ---------------- converts ----------------
template <bool STRAIGHT>
__global__ void cvt_split_T(const float* __restrict__ in, int ldin,
                            __half* __restrict__ oh, __half* __restrict__ ol,
                            __half* __restrict__ sh, __half* __restrict__ sl,
                            int R, int C)
{
    __shared__ float tile[32][33];
    const int c0 = blockIdx.x * 32, r0 = blockIdx.y * 32;
    const int tx = threadIdx.x, ty = threadIdx.y;
    #pragma unroll
    for (int i = 0; i < 32; i += 8) {
        float v = in[(size_t)(r0 + ty + i) * ldin + c0 + tx];
        tile[ty + i][tx] = v;
        if (STRAIGHT) {
            __half h, l;
            split1(v, h, l);
            const size_t o = (size_t)(r0 + ty + i) * C + c0 + tx;
            sh[o] = h;
            sl[o] = l;
        }
    }
    __syncthreads();
    #pragma unroll
    for (int i = 0; i < 32; i += 8) {
        float v = tile[tx][ty + i];
        __half h, l;
        split1(v, h, l);
        const size_t o = (size_t)(c0 + ty + i) * R + r0 + tx;
        oh[o] = h;
        ol[o] = l;
    }
}

__global__ void cvt_T_pair(const float* __restrict__ A, const float* __restrict__ B,
                           __half* __restrict__ oh, __half* __restrict__ ol,
                           int R, int C)
{
    __shared__ float tile[32][33];
    const int z = blockIdx.z;
    const float* in = z ? B : A;
    const size_t zoff = (size_t)z * C * R;
    const int c0 = blockIdx.x * 32, r0 = blockIdx.y * 32;
    const int tx = threadIdx.x, ty = threadIdx.y;
    #pragma unroll
    for (int i = 0; i < 32; i += 8)
        tile[ty + i][tx] = in[(size_t)(r0 + ty + i) * C + c0 + tx];
    __syncthreads();
    #pragma unroll
    for (int i = 0; i < 32; i += 8) {
        float v = tile[tx][ty + i];
        __half h, l;
        split1(v, h, l);
        const size_t o = zoff + (size_t)(c0 + ty + i) * R + r0 + tx;
        oh[o] = h;
        ol[o] = l;
    }
}

// ---------------- register-resident softmax + fp16 split output ----------------
__global__ void softmax_cvt(const float* __restrict__ Sc, __half* __restrict__ Ph,
                            __half* __restrict__ Pl)
{
    const size_t base = (size_t)blockIdx.x * S;
    const int t = threadIdx.x, lane = t & 31, wid = t >> 5;
    __shared__ float red[8];

    float4 v0 = *reinterpret_cast<const float4*>(Sc + base + t * 4);
    float4 v1 = *reinterpret_cast<const float4*>(Sc + base + 1024 + t * 4);
    float m = fmaxf(fmaxf(fmaxf(v0.x, v0.y), fmaxf(v0.z, v0.w)),
                    fmaxf(fmaxf(v1.x, v1.y), fmaxf(v1.z, v1.w)));
    #pragma unroll
    for (int o = 16; o > 0; o >>= 1) m = fmaxf(m, __shfl_xor_sync(0xffffffffu, m, o));
    if (lane == 0) red[wid] = m;
    __syncthreads();
    m = red[0];
    #pragma unroll
    for (int i = 1; i < 8; i++) m = fmaxf(m, red[i]);
    __syncthreads();

    float e[8];
    e[0] = __expf(v0.x - m); e[1] = __expf(v0.y - m);
    e[2] = __expf(v0.z - m); e[3] = __expf(v0.w - m);
    e[4] = __expf(v1.x - m); e[5] = __expf(v1.y - m);
    e[6] = __expf(v1.z - m); e[7] = __expf(v1.w - m);
    float s = e[0] + e[1] + e[2] + e[3] + e[4] + e[5] + e[6] + e[7];
    #pragma unroll
    for (int o = 16; o > 0; o >>= 1) s += __shfl_xor_sync(0xffffffffu, s, o);
    if (lane == 0) red[wid] = s;
    __syncthreads();
    s = red[0];
    #pragma unroll
    for (int i = 1; i < 8; i++) s += red[i];
    const float inv = 1.0f / s;

    #pragma unroll
    for (int half = 0; half < 2; half++) {
        const size_t o = base + half * 1024 + t * 4;
        __half h0, l0, h1, l1, h2, l2, h3, l3;
        split1(e[half * 4 + 0] * inv, h0, l0);
        split1(e[half * 4 + 1] * inv, h1, l1);
        split1(e[half * 4 + 2] * inv, h2, l2);
        split1(e[half * 4 + 3] * inv, h3, l3);
        *reinterpret_cast<__half2*>(Ph + o)     = __halves2half2(h0, h1);
        *reinterpret_cast<__half2*>(Ph + o + 2) = __halves2half2(h2, h3);
        *reinterpret_cast<__half2*>(Pl + o)     = __halves2half2(l0, l1);
        *reinterpret_cast<__half2*>(Pl + o + 2) = __halves2half2(l2, l3);
    }
}

// ---------------- row-wise L2 normalize (strided) ----------------
__global__ void l2norm_rows(float* __restrict__ V, int ld, int cols)
{
    float* row = V + (size_t)blockIdx.x * ld;
    __shared__ float red[128];
    const int t = threadIdx.x;
    float s = 0.f;
    for (int c = t; c < cols; c += 128) { float v = row[c]; s += v * v; }
    red[t] = s; __syncthreads();
    for (int st = 64; st > 0; st >>= 1) { if (t < st) red[t] += red[t + st]; __syncthreads(); }
    const float inv = 1.0f / sqrtf(red[0]);
    for (int c = t; c < cols; c += 128) row[c] *= inv;
}

// ---------------- block-3 tail ----------------
__global__ void rowproj(const float* __restrict__ h, const float* __restrict__ W,
                        const float* __restrict__ b, float* __restrict__ out,
                        int Din, int Nout)
{
    const int n = threadIdx.x;
    if (n >= Nout) return;
    float s = b[n];
    for (int d = 0; d < Din; d++) s = fmaf(h[d], W[(size_t)d * Nout + n], s);
    out[n] = s;
}

__global__ void dotrow(const float* __restrict__ q, const float* __restrict__ Kmat,
                       int ld, float* __restrict__ srow, int Kd)
{
    const int j = blockIdx.x;
    const int t = threadIdx.x;
    float s = 0.f;
    for (int c = t; c < Kd; c += 32) s = fmaf(q[c], Kmat[(size_t)j * ld + c], s);
    #pragma unroll
    for (int o = 16; o > 0; o >>= 1) s += __shfl_down_sync(0xffffffffu, s, o);
    if (t == 0) srow[j] = s;
}

__global__ void zero_out(float* out) { out[threadIdx.x + blockIdx.x * 256] = 0.f; }

// fused softmax (redundant per block) + slice-AV with atomic reduce
__global__ void av_split(const float* __restrict__ srow, const float* __restrict__ V,
                         int ld, float* __restrict__ out)
{
    __shared__ float probs[S];
    __shared__ float red[8];
    const int t = threadIdx.x, lane = t & 31, wid = t >> 5;

    float v[8];
    #pragma unroll
    for (int i = 0; i < 8; i++) v[i] = srow[t + i * 256];
    float m = v[0];
    #pragma unroll
    for (int i = 1; i < 8; i++) m = fmaxf(m, v[i]);
    #pragma unroll
    for (int o = 16; o > 0; o >>= 1) m = fmaxf(m, __shfl_xor_sync(0xffffffffu, m, o));
    if (lane == 0) red[wid] = m;
    __syncthreads();
    m = red[0];
    #pragma unroll
    for (int i = 1; i < 8; i++) m = fmaxf(m, red[i]);
    __syncthreads();

    float s = 0.f;
    #pragma unroll
    for (int i = 0; i < 8; i++) {
        float e = __expf(v[i] - m);
        probs[t + i * 256] = e;
        s += e;
    }
    #pragma unroll
    for (int o = 16; o > 0; o >>= 1) s += __shfl_xor_sync(0xffffffffu, s, o);
    if (lane == 0) red[wid] = s;
    __syncthreads();
    s = red[0];
    #pragma unroll
    for (int i = 1; i < 8; i++) s += red[i];
    const float inv = 1.0f / s;
    __syncthreads();

    const int d = blockIdx.x * 256 + t;
    const int j0 = blockIdx.y * 128;
    float acc = 0.f;
    #pragma unroll 4
    for (int j = j0; j < j0 + 128; j++)
        acc = fmaf(probs[j], V[(size_t)j * ld + d], acc);
    atomicAdd(out + d, acc * inv);
}

// ---------------- launch ----------------
extern "C" void kernel_launch(void* const* d_in, const int* in_sizes, int n_in,
                              void* d_out, int out_size)
{
    const float* x   = (const float*)d_in[0];   // [8,S,D] — batch 0 only
    const float* Wk1 = (const float*)d_in[1];
    const float* bk1 = (const float*)d_in[2];
    const float* Wq1 = (const float*)d_in[3];
    const float* bq1 = (const float*)d_in[4];
    const float* Wk2 = (const float*)d_in[5];
    const float* bk2 = (const float*)d_in[6];
    const float* Wq2 = (const float*)d_in[7];
    const float* bq2 = (const float*)d_in[8];
    const float* Wv2 = (const float*)d_in[9];
    const float* bv2 = (const float*)d_in[10];
    float* out = (float*)d_out;

    float *sc, *qkv32, *h2, *qrow, *srow;
    cudaGetSymbolAddress((void**)&sc,    g_sc);
    cudaGetSymbolAddress((void**)&qkv32, g_qkv32);
    cudaGetSymbolAddress((void**)&h2,    g_h2);
    cudaGetSymbolAddress((void**)&qrow,  g_qrow);
    cudaGetSymbolAddress((void**)&srow,  g_srow);

    __half *xh, *xl, *xTh, *xTl, *wqk1h, *wqk1l, *wqkv2h, *wqkv2l;
    __half *qk1h, *qk1l, *qkvh, *qkvl, *ph, *pl, *h1h, *h1l, *vTh, *vTl, *h2h, *h2l;
    cudaGetSymbolAddress((void**)&xh, g_xh);   cudaGetSymbolAddress((void**)&xl, g_xl);
    cudaGetSymbolAddress((void**)&xTh, g_xTh); cudaGetSymbolAddress((void**)&xTl, g_xTl);
    cudaGetSymbolAddress((void**)&wqk1h, g_wqk1h);   cudaGetSymbolAddress((void**)&wqk1l, g_wqk1l);
    cudaGetSymbolAddress((void**)&wqkv2h, g_wqkv2h); cudaGetSymbolAddress((void**)&wqkv2l, g_wqkv2l);
    cudaGetSymbolAddress((void**)&qk1h, g_qk1h); cudaGetSymbolAddress((void**)&qk1l, g_qk1l);
    cudaGetSymbolAddress((void**)&qkvh, g_qkvh); cudaGetSymbolAddress((void**)&qkvl, g_qkvl);
    cudaGetSymbolAddress((void**)&ph, g_ph); cudaGetSymbolAddress((void**)&pl, g_pl);
    cudaGetSymbolAddress((void**)&h1h, g_h1h); cudaGetSymbolAddress((void**)&h1l, g_h1l);
    cudaGetSymbolAddress((void**)&vTh, g_vTh); cudaGetSymbolAddress((void**)&vTl, g_vTl);
    cudaGetSymbolAddress((void**)&h2h, g_h2h); cudaGetSymbolAddress((void**)&h2l, g_h2l);

    cudaFuncSetAttribute((const void*)mma_gemm<128, 64, 2, 2, 1, 1, 2>,
                         cudaFuncAttributeMaxDynamicSharedMemorySize, SMEMP);
    cudaFuncSetAttribute((const void*)mma_gemm<128, 64, 2, 2, 1, 0, 2>,
                         cudaFuncAttributeMaxDynamicSharedMemorySize, SMEMP);
    cudaFuncSetAttribute((const void*)mma_gemm<128, 64, 2, 2, 2, 2, 2>,
                         cudaFuncAttributeMaxDynamicSharedMemorySize, SMEMP);
    cudaFuncSetAttribute((const void*)mma_gemm<128, 64, 2, 2, 2, 0, 2>,
                         cudaFuncAttributeMaxDynamicSharedMemorySize, SMEMP);
    cudaFuncSetAttribute((const void*)mma_gemm<128, 64, 2, 2, 0, 2, 2>,
                         cudaFuncAttributeMaxDynamicSharedMemorySize, SMEMP);
    cudaFuncSetAttribute((const void*)mma_gemm<256, 128, 4, 2, 0, 0, 1>,
                         cudaFuncAttributeMaxDynamicSharedMemorySize, SMEMS);

    const dim3 gP1(512 / 64, S / 128);    // (8,16)
    const dim3 gP2(1024 / 64, S / 128);   // (16,16)
    const dim3 gScor(S / 128, S / 256);   // (16,8) = 128 CTAs, one wave
    const dim3 gAV(D / 64, S / 128);      // (8,16)
    const dim3 tT(32, 8);

    // ---------- Block 1 ----------
    cvt_split_T<true><<<dim3(D / 32, S / 32), tT>>>(x, D, xTh, xTl, xh, xl, S, D);
    cvt_T_pair<<<dim3(KC / 32, D / 32, 2), tT>>>(Wq1, Wk1, wqk1h, wqk1l, D, KC);
    mma_gemm<128, 64, 2, 2, 1, 1, 2><<<gP1, 128, SMEMP>>>(xh, xl, wqk1h, wqk1l,
        bq1, bk1, nullptr, nullptr, qk1h, qk1l, D, D, D, 512);
    mma_gemm<256, 128, 4, 2, 0, 0, 1><<<gScor, 256, SMEMS>>>(qk1h, qk1l, qk1h + 256, qk1l + 256,
        nullptr, nullptr, nullptr, sc, nullptr, nullptr, KC, 512, 512, S);
    softmax_cvt<<<S, 256>>>(sc, ph, pl);
    mma_gemm<128, 64, 2, 2, 1, 0, 2><<<gAV, 128, SMEMP>>>(ph, pl, xTh, xTl,
        nullptr, nullptr, nullptr, nullptr, h1h, h1l, S, S, S, D);

    // ---------- Block 2 ----------
    cvt_T_pair<<<dim3(KC / 32, D / 32, 2), tT>>>(Wq2, Wk2, wqkv2h, wqkv2l, D, KC);
    cvt_split_T<false><<<dim3(D / 32, D / 32), tT>>>(Wv2, D, wqkv2h + 512 * D, wqkv2l + 512 * D,
        nullptr, nullptr, D, D);
    mma_gemm<128, 64, 2, 2, 2, 2, 2><<<gP2, 128, SMEMP>>>(h1h, h1l, wqkv2h, wqkv2l,
        bq2, bk2, bv2, qkv32, qkvh, qkvl, D, D, D, 1024);
    l2norm_rows<<<S, 128>>>(qkv32 + 512, 1024, D);
    cvt_split_T<false><<<dim3(D / 32, S / 32), tT>>>(qkv32 + 512, 1024, vTh, vTl,
        nullptr, nullptr, S, D);
    mma_gemm<256, 128, 4, 2, 0, 0, 1><<<gScor, 256, SMEMS>>>(qkvh, qkvl, qkvh + 256, qkvl + 256,
        nullptr, nullptr, nullptr, sc, nullptr, nullptr, KC, 1024, 1024, S);
    softmax_cvt<<<S, 256>>>(sc, ph, pl);
    mma_gemm<128, 64, 2, 2, 2, 0, 2><<<gAV, 128, SMEMP>>>(ph, pl, vTh, vTl,
        nullptr, nullptr, nullptr, h2, h2h, h2l, S, S, S, D);

    // ---------- Block 3 (only last query row needed) ----------
    mma_gemm<128, 64, 2, 2, 0, 2, 2><<<gP2, 128, SMEMP>>>(h2h, h2l, wqkv2h, wqkv2l,
        bq2, bk2, bv2, qkv32, nullptr, nullptr, D, D, D, 1024);
    l2norm_rows<<<S, 128>>>(qkv32 + 512, 1024, D);
    rowproj<<<1, KC>>>(h2 + (size_t)(S - 1) * D, Wq2, bq2, qrow, D, KC);
    dotrow<<<S, 32>>>(qrow, qkv32 + 256, 1024, srow, KC);
    zero_out<<<2, 256>>>(out);
    av_split<<<dim3(2, 16), 256>>>(srow, qkv32 + 512, 1024, out);
}

// round 11
// speedup vs baseline: 1.0411x; 1.0053x over previous
#include <cuda_runtime.h>
#include <cuda_fp16.h>
#include <cstdint>

// Shapes (fixed)
#define S  2048
#define D  512
#define KC 256

// ---------------- fp32 scratch ----------------
__device__ float g_sc[(size_t)S * S];       // scores
__device__ float g_qkv32[S * 1024];         // packed q|k|v fp32 (blocks 2/3)
__device__ float g_h2[S * D];               // block-2 output fp32
__device__ float g_qrow[KC];
__device__ float g_srow[S];

// ---------------- fp16 hi/lo scratch (16B aligned) ----------------
#define HBUF(name, n) __device__ __align__(16) __half name[n]
HBUF(g_xh,  S * D);   HBUF(g_xl,  S * D);
HBUF(g_xTh, D * S);   HBUF(g_xTl, D * S);
HBUF(g_wqk1h, 512 * D);  HBUF(g_wqk1l, 512 * D);     // [Wq1;Wk1] K-major
HBUF(g_wqkv2h, 1024 * D); HBUF(g_wqkv2l, 1024 * D);  // [Wq2;Wk2;Wv2] K-major
HBUF(g_qk1h, S * 512);  HBUF(g_qk1l, S * 512);
HBUF(g_qkvh, S * 1024); HBUF(g_qkvl, S * 1024);
HBUF(g_ph, (size_t)S * S);  HBUF(g_pl, (size_t)S * S);
HBUF(g_h1h, S * D);  HBUF(g_h1l, S * D);
HBUF(g_vTh, D * S);  HBUF(g_vTl, D * S);
HBUF(g_h2h, S * D);  HBUF(g_h2l, S * D);

// ---------------- helpers ----------------
__device__ __forceinline__ uint32_t smem_u32(const void* p) {
    uint32_t a;
    asm("{ .reg .u64 t; cvta.to.shared.u64 t, %1; cvt.u32.u64 %0, t; }" : "=r"(a) : "l"(p));
    return a;
}
__device__ __forceinline__ void ldsm4(uint32_t* r, uint32_t a) {
    asm volatile("ldmatrix.sync.aligned.m8n8.x4.shared.b16 {%0,%1,%2,%3}, [%4];"
                 : "=r"(r[0]), "=r"(r[1]), "=r"(r[2]), "=r"(r[3]) : "r"(a));
}
__device__ __forceinline__ void mma_f16(float* c, const uint32_t* a, const uint32_t* b) {
    asm volatile(
        "mma.sync.aligned.m16n8k16.row.col.f32.f16.f16.f32 "
        "{%0,%1,%2,%3}, {%4,%5,%6,%7}, {%8,%9}, {%0,%1,%2,%3};"
        : "+f"(c[0]), "+f"(c[1]), "+f"(c[2]), "+f"(c[3])
        : "r"(a[0]), "r"(a[1]), "r"(a[2]), "r"(a[3]), "r"(b[0]), "r"(b[1]));
}
__device__ __forceinline__ void cp16(uint32_t dst, const void* src) {
    asm volatile("cp.async.cg.shared.global [%0], [%1], 16;" :: "r"(dst), "l"(src));
}
#define CP_COMMIT() asm volatile("cp.async.commit_group;" ::: "memory")
#define CP_WAIT1()  asm volatile("cp.async.wait_group 1;" ::: "memory")

__device__ __forceinline__ void split1(float v, __half& h, __half& l) {
    h = __float2half_rn(v);
    l = __float2half_rn(v - __half2float(h));
}

// ---------------- fp16 hi/lo split tensor-core GEMM ----------------
// C[M,N] = (Ah+Al)[M,K] * (Bh+Bl)[N,K]^T + bias.  K-major fp16 operands.
// OUT: 0 = fp32 C; 1 = fp16 Ch/Cl; 2 = both.
// BMODE: 0 none; 1 two-way bias split at col 256; 2 three-way at 256/512.
// OCC: min CTAs/SM.  NSTAGE: cp.async pipeline depth (2 or 3).
#define ROWB 80

template <int BM, int BN, int WM, int WN, int OUT, int BMODE, int OCC, int NSTAGE>
__global__ void __launch_bounds__(WM* WN * 32, OCC) mma_gemm(
    const __half* __restrict__ Ah, const __half* __restrict__ Al,
    const __half* __restrict__ Bh, const __half* __restrict__ Bl,
    const float* __restrict__ Bi0, const float* __restrict__ Bi1,
    const float* __restrict__ Bi2,
    float* __restrict__ C, __half* __restrict__ Ch, __half* __restrict__ Cl,
    int K, int lda, int ldb, int ldc)
{
    constexpr int T = WM * WN * 32;
    constexpr int WTM = BM / WM, WTN = BN / WN;
    constexpr int MT = WTM / 16, NT = WTN / 8;
    constexpr int ATILE = BM * ROWB;
    constexpr int BTILE = BN * ROWB;
    constexpr int STAGE = 2 * ATILE + 2 * BTILE;

    extern __shared__ char smc[];
    const uint32_t sb0 = smem_u32(smc);
    const int t = threadIdx.x, lane = t & 31, wid = t >> 5;
    const int wm = (wid % WM) * WTM, wn = (wid / WM) * WTN;
    const int m0 = blockIdx.y * BM, n0 = blockIdx.x * BN;

    float acc[MT][NT][4];
    #pragma unroll
    for (int i = 0; i < MT; i++)
        #pragma unroll
        for (int j = 0; j < NT; j++)
            #pragma unroll
            for (int k = 0; k < 4; k++) acc[i][j][k] = 0.f;

    const int NC = K >> 5;

    auto cp_chunk = [&](uint32_t st, int k0) {
        #pragma unroll
        for (int i = 0; i < (BM * 4) / T; i++) {
            int v = t + i * T; int r = v >> 2, s = v & 3;
            uint32_t d = st + (uint32_t)(r * ROWB + s * 16);
            const size_t o = (size_t)(m0 + r) * lda + k0 + s * 8;
            cp16(d, Ah + o);
            cp16(d + ATILE, Al + o);
        }
        #pragma unroll
        for (int i = 0; i < (BN * 4) / T; i++) {
            int v = t + i * T; int r = v >> 2, s = v & 3;
            uint32_t d = st + 2 * ATILE + (uint32_t)(r * ROWB + s * 16);
            const size_t o = (size_t)(n0 + r) * ldb + k0 + s * 8;
            cp16(d, Bh + o);
            cp16(d + BTILE, Bl + o);
        }
    };

    auto mma_stage = [&](uint32_t st) {
        const int l7 = lane & 7, mt = lane >> 3;
        #pragma unroll
        for (int ks = 0; ks < 2; ks++) {
            uint32_t af_h[MT][4], af_l[MT][4];
            #pragma unroll
            for (int mi = 0; mi < MT; mi++) {
                uint32_t ra = st + (uint32_t)((wm + mi * 16 + l7 + ((mt & 1) << 3)) * ROWB
                                              + ks * 32 + ((mt >> 1) << 4));
                ldsm4(af_h[mi], ra);
                ldsm4(af_l[mi], ra + ATILE);
            }
            uint32_t bf_h[NT][2], bf_l[NT][2];
            #pragma unroll
            for (int np = 0; np < NT / 2; np++) {
                uint32_t rb = st + 2 * ATILE
                            + (uint32_t)((wn + np * 16 + ((mt >> 1) << 3) + l7) * ROWB
                                         + ks * 32 + ((mt & 1) << 4));
                uint32_t r4[4];
                ldsm4(r4, rb);
                bf_h[2 * np][0] = r4[0]; bf_h[2 * np][1] = r4[1];
                bf_h[2 * np + 1][0] = r4[2]; bf_h[2 * np + 1][1] = r4[3];
                ldsm4(r4, rb + BTILE);
                bf_l[2 * np][0] = r4[0]; bf_l[2 * np][1] = r4[1];
                bf_l[2 * np + 1][0] = r4[2]; bf_l[2 * np + 1][1] = r4[3];
            }
            #pragma unroll
            for (int mi = 0; mi < MT; mi++)
                #pragma unroll
                for (int ni = 0; ni < NT; ni++) {
                    mma_f16(acc[mi][ni], af_h[mi], bf_h[ni]);
                    mma_f16(acc[mi][ni], af_h[mi], bf_l[ni]);
                    mma_f16(acc[mi][ni], af_l[mi], bf_h[ni]);
                }
        }
    };

    cp_chunk(sb0, 0);
    CP_COMMIT();
    if (NC > 1) cp_chunk(sb0 + STAGE, 32);
    CP_COMMIT();
    for (int c = 0; c < NC; c++) {
        CP_WAIT1();
        __syncthreads();
        mma_stage(sb0 + (uint32_t)((c % NSTAGE) * STAGE));
        // NSTAGE==3: cp(c+2) writes buffer (c-1)%3 whose readers passed the
        // barrier at the top of iter c — no barrier needed.
        // NSTAGE==2: cp(c+2) reuses mma(c)'s buffer — must barrier first.
        if (NSTAGE == 2) __syncthreads();
        if (c + 2 < NC) cp_chunk(sb0 + (uint32_t)(((c + 2) % NSTAGE) * STAGE), (c + 2) * 32);
        CP_COMMIT();
    }

    // epilogue
    const int g = lane >> 2, w2 = (lane & 3) * 2;
    #pragma unroll
    for (int ni = 0; ni < NT; ni++) {
        const int col = n0 + wn + ni * 8 + w2;
        float b0v = 0.f, b1v = 0.f;
        if (BMODE == 1) {
            const float* bp = (col < 256) ? Bi0 : (Bi1 - 256);
            b0v = bp[col]; b1v = bp[col + 1];
        } else if (BMODE == 2) {
            const float* bp = (col < 256) ? Bi0 : (col < 512 ? (Bi1 - 256) : (Bi2 - 512));
            b0v = bp[col]; b1v = bp[col + 1];
        }
        #pragma unroll
        for (int mi = 0; mi < MT; mi++) {
            const int row = m0 + wm + mi * 16 + g;
            float c00 = acc[mi][ni][0] + b0v, c01 = acc[mi][ni][1] + b1v;
            float c10 = acc[mi][ni][2] + b0v, c11 = acc[mi][ni][3] + b1v;
            if (OUT == 0 || OUT == 2) {
                *reinterpret_cast<float2*>(&C[(size_t)row * ldc + col]) = make_float2(c00, c01);
                *reinterpret_cast<float2*>(&C[(size_t)(row + 8) * ldc + col]) = make_float2(c10, c11);
            }
            if (OUT >= 1) {
                __half h0, l0, h1, l1;
                split1(c00, h0, l0); split1(c01, h1, l1);
                *reinterpret_cast<__half2*>(&Ch[(size_t)row * ldc + col]) = __halves2half2(h0, h1);
                *reinterpret_cast<__half2*>(&Cl[(size_t)row * ldc + col]) = __halves2half2(l0, l1);
                split1(c10, h0, l0); split1(c11, h1, l1);
                *reinterpret_cast<__half2*>(&Ch[(size_t)(row + 8) * ldc + col]) = __halves2half2(h0, h1);
                *reinterpret_cast<__half2*>(&Cl[(size_t)(row + 8) * ldc + col]) = __halves2half2(l0, l1);
            }
        }
    }
}

// proj/AV: 128x64 tile, 256 thr (8 warps, warp 32x32), 3-stage, 2 CTAs/SM
#define SMEMP  (3 * (2 * 128 * ROWB + 2 * 64 * ROWB))       // 92160
// scores: 128x128 tile, 256 thr (8 warps, warp 64x32), 2-stage, 2 CTAs/SM
#define SMEMS  (2 * (2 * 128 * ROWB + 2 * 128 * ROWB))      // 81920

// ---------------- converts ----------------
template <bool STRAIGHT>
__global__ void cvt_split_T(const float* __restrict__ in, int ldin,
                            __half* __restrict__ oh, __half* __restrict__ ol,
                            __half* __restrict__ sh, __half* __restrict__ sl,
                            int R, int C)
{
    __shared__ float tile[32][33];
    const int c0 = blockIdx.x * 32, r0 = blockIdx.y * 32;
    const int tx = threadIdx.x, ty = threadIdx.y;
    #pragma unroll
    for (int i = 0; i < 32; i += 8) {
        float v = in[(size_t)(r0 + ty + i) * ldin + c0 + tx];
        tile[ty + i][tx] = v;
        if (STRAIGHT) {
            __half h, l;
            split1(v, h, l);
            const size_t o = (size_t)(r0 + ty + i) * C + c0 + tx;
            sh[o] = h;
            sl[o] = l;
        }
    }
    __syncthreads();
    #pragma unroll
    for (int i = 0; i < 32; i += 8) {
        float v = tile[tx][ty + i];
        __half h, l;
        split1(v, h, l);
        const size_t o = (size_t)(c0 + ty + i) * R + r0 + tx;
        oh[o] = h;
        ol[o] = l;
    }
}

__global__ void cvt_T_pair(const float* __restrict__ A, const float* __restrict__ B,
                           __half* __restrict__ oh, __half* __restrict__ ol,
                           int R, int C)
{
    __shared__ float tile[32][33];
    const int z = blockIdx.z;
    const float* in = z ? B : A;
    const size_t zoff = (size_t)z * C * R;
    const int c0 = blockIdx.x * 32, r0 = blockIdx.y * 32;
    const int tx = threadIdx.x, ty = threadIdx.y;
    #pragma unroll
    for (int i = 0; i < 32; i += 8)
        tile[ty + i][tx] = in[(size_t)(r0 + ty + i) * C + c0 + tx];
    __syncthreads();
    #pragma unroll
    for (int i = 0; i < 32; i += 8) {
        float v = tile[tx][ty + i];
        __half h, l;
        split1(v, h, l);
        const size_t o = zoff + (size_t)(c0 + ty + i) * R + r0 + tx;
        oh[o] = h;
        ol[o] = l;
    }
}

// ---------------- register-resident softmax + fp16 split output ----------------
__global__ void softmax_cvt(const float* __restrict__ Sc, __half* __restrict__ Ph,
                            __half* __restrict__ Pl)
{
    const size_t base = (size_t)blockIdx.x * S;
    const int t = threadIdx.x, lane = t & 31, wid = t >> 5;
    __shared__ float red[8];

    float4 v0 = *reinterpret_cast<const float4*>(Sc + base + t * 4);
    float4 v1 = *reinterpret_cast<const float4*>(Sc + base + 1024 + t * 4);
    float m = fmaxf(fmaxf(fmaxf(v0.x, v0.y), fmaxf(v0.z, v0.w)),
                    fmaxf(fmaxf(v1.x, v1.y), fmaxf(v1.z, v1.w)));
    #pragma unroll
    for (int o = 16; o > 0; o >>= 1) m = fmaxf(m, __shfl_xor_sync(0xffffffffu, m, o));
    if (lane == 0) red[wid] = m;
    __syncthreads();
    m = red[0];
    #pragma unroll
    for (int i = 1; i < 8; i++) m = fmaxf(m, red[i]);
    __syncthreads();

    float e[8];
    e[0] = __expf(v0.x - m); e[1] = __expf(v0.y - m);
    e[2] = __expf(v0.z - m); e[3] = __expf(v0.w - m);
    e[4] = __expf(v1.x - m); e[5] = __expf(v1.y - m);
    e[6] = __expf(v1.z - m); e[7] = __expf(v1.w - m);
    float s = e[0] + e[1] + e[2] + e[3] + e[4] + e[5] + e[6] + e[7];
    #pragma unroll
    for (int o = 16; o > 0; o >>= 1) s += __shfl_xor_sync(0xffffffffu, s, o);
    if (lane == 0) red[wid] = s;
    __syncthreads();
    s = red[0];
    #pragma unroll
    for (int i = 1; i < 8; i++) s += red[i];
    const float inv = 1.0f / s;

    #pragma unroll
    for (int half = 0; half < 2; half++) {
        const size_t o = base + half * 1024 + t * 4;
        __half h0, l0, h1, l1, h2, l2, h3, l3;
        split1(e[half * 4 + 0] * inv, h0, l0);
        split1(e[half * 4 + 1] * inv, h1, l1);
        split1(e[half * 4 + 2] * inv, h2, l2);
        split1(e[half * 4 + 3] * inv, h3, l3);
        *reinterpret_cast<__half2*>(Ph + o)     = __halves2half2(h0, h1);
        *reinterpret_cast<__half2*>(Ph + o + 2) = __halves2half2(h2, h3);
        *reinterpret_cast<__half2*>(Pl + o)     = __halves2half2(l0, l1);
        *reinterpret_cast<__half2*>(Pl + o + 2) = __halves2half2(l2, l3);
    }
}

// ---------------- row-wise L2 normalize (strided) ----------------
__global__ void l2norm_rows(float* __restrict__ V, int ld, int cols)
{
    float* row = V + (size_t)blockIdx.x * ld;
    __shared__ float red[128];
    const int t = threadIdx.x;
    float s = 0.f;
    for (int c = t; c < cols; c += 128) { float v = row[c]; s += v * v; }
    red[t] = s; __syncthreads();
    for (int st = 64; st > 0; st >>= 1) { if (t < st) red[t] += red[t + st]; __syncthreads(); }
    const float inv = 1.0f / sqrtf(red[0]);
    for (int c = t; c < cols; c += 128) row[c] *= inv;
}

// ---------------- block-3 tail ----------------
__global__ void rowproj(const float* __restrict__ h, const float* __restrict__ W,
                        const float* __restrict__ b, float* __restrict__ out,
                        int Din, int Nout)
{
    const int n = threadIdx.x;
    if (n >= Nout) return;
    float s = b[n];
    for (int d = 0; d < Din; d++) s = fmaf(h[d], W[(size_t)d * Nout + n], s);
    out[n] = s;
}

__global__ void dotrow(const float* __restrict__ q, const float* __restrict__ Kmat,
                       int ld, float* __restrict__ srow, int Kd)
{
    const int j = blockIdx.x;
    const int t = threadIdx.x;
    float s = 0.f;
    for (int c = t; c < Kd; c += 32) s = fmaf(q[c], Kmat[(size_t)j * ld + c], s);
    #pragma unroll
    for (int o = 16; o > 0; o >>= 1) s += __shfl_down_sync(0xffffffffu, s, o);
    if (t == 0) srow[j] = s;
}

__global__ void zero_out(float* out) { out[threadIdx.x + blockIdx.x * 256] = 0.f; }

// fused softmax (redundant per block) + slice-AV with atomic reduce
__global__ void av_split(const float* __restrict__ srow, const float* __restrict__ V,
                         int ld, float* __restrict__ out)
{
    __shared__ float probs[S];
    __shared__ float red[8];
    const int t = threadIdx.x, lane = t & 31, wid = t >> 5;

    float v[8];
    #pragma unroll
    for (int i = 0; i < 8; i++) v[i] = srow[t + i * 256];
    float m = v[0];
    #pragma unroll
    for (int i = 1; i < 8; i++) m = fmaxf(m, v[i]);
    #pragma unroll
    for (int o = 16; o > 0; o >>= 1) m = fmaxf(m, __shfl_xor_sync(0xffffffffu, m, o));
    if (lane == 0) red[wid] = m;
    __syncthreads();
    m = red[0];
    #pragma unroll
    for (int i = 1; i < 8; i++) m = fmaxf(m, red[i]);
    __syncthreads();

    float s = 0.f;
    #pragma unroll
    for (int i = 0; i < 8; i++) {
        float e = __expf(v[i] - m);
        probs[t + i * 256] = e;
        s += e;
    }
    #pragma unroll
    for (int o = 16; o > 0; o >>= 1) s += __shfl_xor_sync(0xffffffffu, s, o);
    if (lane == 0) red[wid] = s;
    __syncthreads();
    s = red[0];
    #pragma unroll
    for (int i = 1; i < 8; i++) s += red[i];
    const float inv = 1.0f / s;
    __syncthreads();

    const int d = blockIdx.x * 256 + t;
    const int j0 = blockIdx.y * 128;
    float acc = 0.f;
    #pragma unroll 4
    for (int j = j0; j < j0 + 128; j++)
        acc = fmaf(probs[j], V[(size_t)j * ld + d], acc);
    atomicAdd(out + d, acc * inv);
}

// ---------------- launch ----------------
extern "C" void kernel_launch(void* const* d_in, const int* in_sizes, int n_in,
                              void* d_out, int out_size)
{
    const float* x   = (const float*)d_in[0];   // [8,S,D] — batch 0 only
    const float* Wk1 = (const float*)d_in[1];
    const float* bk1 = (const float*)d_in[2];
    const float* Wq1 = (const float*)d_in[3];
    const float* bq1 = (const float*)d_in[4];
    const float* Wk2 = (const float*)d_in[5];
    const float* bk2 = (const float*)d_in[6];
    const float* Wq2 = (const float*)d_in[7];
    const float* bq2 = (const float*)d_in[8];
    const float* Wv2 = (const float*)d_in[9];
    const float* bv2 = (const float*)d_in[10];
    float* out = (float*)d_out;

    float *sc, *qkv32, *h2, *qrow, *srow;
    cudaGetSymbolAddress((void**)&sc,    g_sc);
    cudaGetSymbolAddress((void**)&qkv32, g_qkv32);
    cudaGetSymbolAddress((void**)&h2,    g_h2);
    cudaGetSymbolAddress((void**)&qrow,  g_qrow);
    cudaGetSymbolAddress((void**)&srow,  g_srow);

    __half *xh, *xl, *xTh, *xTl, *wqk1h, *wqk1l, *wqkv2h, *wqkv2l;
    __half *qk1h, *qk1l, *qkvh, *qkvl, *ph, *pl, *h1h, *h1l, *vTh, *vTl, *h2h, *h2l;
    cudaGetSymbolAddress((void**)&xh, g_xh);   cudaGetSymbolAddress((void**)&xl, g_xl);
    cudaGetSymbolAddress((void**)&xTh, g_xTh); cudaGetSymbolAddress((void**)&xTl, g_xTl);
    cudaGetSymbolAddress((void**)&wqk1h, g_wqk1h);   cudaGetSymbolAddress((void**)&wqk1l, g_wqk1l);
    cudaGetSymbolAddress((void**)&wqkv2h, g_wqkv2h); cudaGetSymbolAddress((void**)&wqkv2l, g_wqkv2l);
    cudaGetSymbolAddress((void**)&qk1h, g_qk1h); cudaGetSymbolAddress((void**)&qk1l, g_qk1l);
    cudaGetSymbolAddress((void**)&qkvh, g_qkvh); cudaGetSymbolAddress((void**)&qkvl, g_qkvl);
    cudaGetSymbolAddress((void**)&ph, g_ph); cudaGetSymbolAddress((void**)&pl, g_pl);
    cudaGetSymbolAddress((void**)&h1h, g_h1h); cudaGetSymbolAddress((void**)&h1l, g_h1l);
    cudaGetSymbolAddress((void**)&vTh, g_vTh); cudaGetSymbolAddress((void**)&vTl, g_vTl);
    cudaGetSymbolAddress((void**)&h2h, g_h2h); cudaGetSymbolAddress((void**)&h2l, g_h2l);

    cudaFuncSetAttribute((const void*)mma_gemm<128, 64, 4, 2, 1, 1, 2, 3>,
                         cudaFuncAttributeMaxDynamicSharedMemorySize, SMEMP);
    cudaFuncSetAttribute((const void*)mma_gemm<128, 64, 4, 2, 1, 0, 2, 3>,
                         cudaFuncAttributeMaxDynamicSharedMemorySize, SMEMP);
    cudaFuncSetAttribute((const void*)mma_gemm<128, 64, 4, 2, 2, 2, 2, 3>,
                         cudaFuncAttributeMaxDynamicSharedMemorySize, SMEMP);
    cudaFuncSetAttribute((const void*)mma_gemm<128, 64, 4, 2, 2, 0, 2, 3>,
                         cudaFuncAttributeMaxDynamicSharedMemorySize, SMEMP);
    cudaFuncSetAttribute((const void*)mma_gemm<128, 64, 4, 2, 0, 2, 2, 3>,
                         cudaFuncAttributeMaxDynamicSharedMemorySize, SMEMP);
    cudaFuncSetAttribute((const void*)mma_gemm<128, 128, 2, 4, 0, 0, 2, 2>,
                         cudaFuncAttributeMaxDynamicSharedMemorySize, SMEMS);

    const dim3 gP1(512 / 64, S / 128);    // (8,16)
    const dim3 gP2(1024 / 64, S / 128);   // (16,16)
    const dim3 gScor(S / 128, S / 128);   // (16,16) = 256 CTAs, 2 per SM
    const dim3 gAV(D / 64, S / 128);      // (8,16)
    const dim3 tT(32, 8);

    // ---------- Block 1 ----------
    cvt_split_T<true><<<dim3(D / 32, S / 32), tT>>>(x, D, xTh, xTl, xh, xl, S, D);
    cvt_T_pair<<<dim3(KC / 32, D / 32, 2), tT>>>(Wq1, Wk1, wqk1h, wqk1l, D, KC);
    mma_gemm<128, 64, 4, 2, 1, 1, 2, 3><<<gP1, 256, SMEMP>>>(xh, xl, wqk1h, wqk1l,
        bq1, bk1, nullptr, nullptr, qk1h, qk1l, D, D, D, 512);
    mma_gemm<128, 128, 2, 4, 0, 0, 2, 2><<<gScor, 256, SMEMS>>>(qk1h, qk1l, qk1h + 256, qk1l + 256,
        nullptr, nullptr, nullptr, sc, nullptr, nullptr, KC, 512, 512, S);
    softmax_cvt<<<S, 256>>>(sc, ph, pl);
    mma_gemm<128, 64, 4, 2, 1, 0, 2, 3><<<gAV, 256, SMEMP>>>(ph, pl, xTh, xTl,
        nullptr, nullptr, nullptr, nullptr, h1h, h1l, S, S, S, D);

    // ---------- Block 2 ----------
    cvt_T_pair<<<dim3(KC / 32, D / 32, 2), tT>>>(Wq2, Wk2, wqkv2h, wqkv2l, D, KC);
    cvt_split_T<false><<<dim3(D / 32, D / 32), tT>>>(Wv2, D, wqkv2h + 512 * D, wqkv2l + 512 * D,
        nullptr, nullptr, D, D);
    mma_gemm<128, 64, 4, 2, 2, 2, 2, 3><<<gP2, 256, SMEMP>>>(h1h, h1l, wqkv2h, wqkv2l,
        bq2, bk2, bv2, qkv32, qkvh, qkvl, D, D, D, 1024);
    l2norm_rows<<<S, 128>>>(qkv32 + 512, 1024, D);
    cvt_split_T<false><<<dim3(D / 32, S / 32), tT>>>(qkv32 + 512, 1024, vTh, vTl,
        nullptr, nullptr, S, D);
    mma_gemm<128, 128, 2, 4, 0, 0, 2, 2><<<gScor, 256, SMEMS>>>(qkvh, qkvl, qkvh + 256, qkvl + 256,
        nullptr, nullptr, nullptr, sc, nullptr, nullptr, KC, 1024, 1024, S);
    softmax_cvt<<<S, 256>>>(sc, ph, pl);
    mma_gemm<128, 64, 4, 2, 2, 0, 2, 3><<<gAV, 256, SMEMP>>>(ph, pl, vTh, vTl,
        nullptr, nullptr, nullptr, h2, h2h, h2l, S, S, S, D);

    // ---------- Block 3 (only last query row needed) ----------
    mma_gemm<128, 64, 4, 2, 0, 2, 2, 3><<<gP2, 256, SMEMP>>>(h2h, h2l, wqkv2h, wqkv2l,
        bq2, bk2, bv2, qkv32, nullptr, nullptr, D, D, D, 1024);
    l2norm_rows<<<S, 128>>>(qkv32 + 512, 1024, D);
    rowproj<<<1, KC>>>(h2 + (size_t)(S - 1) * D, Wq2, bq2, qrow, D, KC);
    dotrow<<<S, 32>>>(qrow, qkv32 + 256, 1024, srow, KC);
    zero_out<<<2, 256>>>(out);
    av_split<<<dim3(2, 16), 256>>>(srow, qkv32 + 512, 1024, out);
}

// round 12
// speedup vs baseline: 1.0569x; 1.0152x over previous
#include <cuda_runtime.h>
#include <cuda_fp16.h>
#include <cstdint>

// Shapes (fixed)
#define S  2048
#define D  512
#define KC 256

// ---------------- fp32 scratch ----------------
__device__ float g_sc[(size_t)S * S];       // scores
__device__ float g_qkv32[S * 1024];         // packed q|k|v fp32 (blocks 2/3)
__device__ float g_h2[S * D];               // block-2 output fp32
__device__ float g_qrow[KC];
__device__ float g_srow[S];

// ---------------- fp16 hi/lo scratch (16B aligned) ----------------
#define HBUF(name, n) __device__ __align__(16) __half name[n]
HBUF(g_xh,  S * D);   HBUF(g_xl,  S * D);
HBUF(g_xTh, D * S);   HBUF(g_xTl, D * S);
HBUF(g_wqk1h, 512 * D);  HBUF(g_wqk1l, 512 * D);     // [Wq1;Wk1] K-major
HBUF(g_wqkv2h, 1024 * D); HBUF(g_wqkv2l, 1024 * D);  // [Wq2;Wk2;Wv2] K-major
HBUF(g_qk1h, S * 512);  HBUF(g_qk1l, S * 512);
HBUF(g_qkvh, S * 1024); HBUF(g_qkvl, S * 1024);
HBUF(g_ph, (size_t)S * S);  HBUF(g_pl, (size_t)S * S);
HBUF(g_h1h, S * D);  HBUF(g_h1l, S * D);
HBUF(g_vTh, D * S);  HBUF(g_vTl, D * S);
HBUF(g_h2h, S * D);  HBUF(g_h2l, S * D);

// ---------------- helpers ----------------
__device__ __forceinline__ uint32_t smem_u32(const void* p) {
    uint32_t a;
    asm("{ .reg .u64 t; cvta.to.shared.u64 t, %1; cvt.u32.u64 %0, t; }" : "=r"(a) : "l"(p));
    return a;
}
__device__ __forceinline__ void ldsm4(uint32_t* r, uint32_t a) {
    asm volatile("ldmatrix.sync.aligned.m8n8.x4.shared.b16 {%0,%1,%2,%3}, [%4];"
                 : "=r"(r[0]), "=r"(r[1]), "=r"(r[2]), "=r"(r[3]) : "r"(a));
}
// fp32-accumulator MMA (main hi*hi term)
__device__ __forceinline__ void mma_f16(float* c, const uint32_t* a, const uint32_t* b) {
    asm volatile(
        "mma.sync.aligned.m16n8k16.row.col.f32.f16.f16.f32 "
        "{%0,%1,%2,%3}, {%4,%5,%6,%7}, {%8,%9}, {%0,%1,%2,%3};"
        : "+f"(c[0]), "+f"(c[1]), "+f"(c[2]), "+f"(c[3])
        : "r"(a[0]), "r"(a[1]), "r"(a[2]), "r"(a[3]), "r"(b[0]), "r"(b[1]));
}
// fp16-accumulator MMA (tiny cross-correction terms)
__device__ __forceinline__ void mma_f16a(uint32_t* c, const uint32_t* a, const uint32_t* b) {
    asm volatile(
        "mma.sync.aligned.m16n8k16.row.col.f16.f16.f16.f16 "
        "{%0,%1}, {%2,%3,%4,%5}, {%6,%7}, {%0,%1};"
        : "+r"(c[0]), "+r"(c[1])
        : "r"(a[0]), "r"(a[1]), "r"(a[2]), "r"(a[3]), "r"(b[0]), "r"(b[1]));
}
__device__ __forceinline__ void cp16(uint32_t dst, const void* src) {
    asm volatile("cp.async.cg.shared.global [%0], [%1], 16;" :: "r"(dst), "l"(src));
}
#define CP_COMMIT() asm volatile("cp.async.commit_group;" ::: "memory")
#define CP_WAIT1()  asm volatile("cp.async.wait_group 1;" ::: "memory")

__device__ __forceinline__ void split1(float v, __half& h, __half& l) {
    h = __float2half_rn(v);
    l = __float2half_rn(v - __half2float(h));
}

// ---------------- fp16 hi/lo split tensor-core GEMM ----------------
// C[M,N] = (Ah+Al)[M,K] * (Bh+Bl)[N,K]^T + bias.  K-major fp16 operands.
// hi*hi term in fp32 accumulators; hi*lo + lo*hi corrections accumulate in a
// shared fp16 accumulator and are added at the epilogue.
// OUT: 0 = fp32 C; 1 = fp16 Ch/Cl; 2 = both.
// BMODE: 0 none; 1 two-way bias split at col 256; 2 three-way at 256/512.
#define ROWB 80

template <int BM, int BN, int WM, int WN, int OUT, int BMODE>
__global__ void __launch_bounds__(WM* WN * 32, 2) mma_gemm(
    const __half* __restrict__ Ah, const __half* __restrict__ Al,
    const __half* __restrict__ Bh, const __half* __restrict__ Bl,
    const float* __restrict__ Bi0, const float* __restrict__ Bi1,
    const float* __restrict__ Bi2,
    float* __restrict__ C, __half* __restrict__ Ch, __half* __restrict__ Cl,
    int K, int lda, int ldb, int ldc)
{
    constexpr int T = WM * WN * 32;
    constexpr int WTM = BM / WM, WTN = BN / WN;
    constexpr int MT = WTM / 16, NT = WTN / 8;
    constexpr int ATILE = BM * ROWB;
    constexpr int BTILE = BN * ROWB;
    constexpr int STAGE = 2 * ATILE + 2 * BTILE;

    extern __shared__ char smc[];
    const uint32_t sb0 = smem_u32(smc);
    const int t = threadIdx.x, lane = t & 31, wid = t >> 5;
    const int wm = (wid % WM) * WTM, wn = (wid / WM) * WTN;
    const int m0 = blockIdx.y * BM, n0 = blockIdx.x * BN;

    float acc[MT][NT][4];
    uint32_t acc16[MT][NT][2];
    #pragma unroll
    for (int i = 0; i < MT; i++)
        #pragma unroll
        for (int j = 0; j < NT; j++) {
            #pragma unroll
            for (int k = 0; k < 4; k++) acc[i][j][k] = 0.f;
            acc16[i][j][0] = 0u;
            acc16[i][j][1] = 0u;
        }

    const int NC = K >> 5;

    auto cp_chunk = [&](uint32_t st, int k0) {
        #pragma unroll
        for (int i = 0; i < (BM * 4) / T; i++) {
            int v = t + i * T; int r = v >> 2, s = v & 3;
            uint32_t d = st + (uint32_t)(r * ROWB + s * 16);
            const size_t o = (size_t)(m0 + r) * lda + k0 + s * 8;
            cp16(d, Ah + o);
            cp16(d + ATILE, Al + o);
        }
        #pragma unroll
        for (int i = 0; i < (BN * 4) / T; i++) {
            int v = t + i * T; int r = v >> 2, s = v & 3;
            uint32_t d = st + 2 * ATILE + (uint32_t)(r * ROWB + s * 16);
            const size_t o = (size_t)(n0 + r) * ldb + k0 + s * 8;
            cp16(d, Bh + o);
            cp16(d + BTILE, Bl + o);
        }
    };

    auto mma_stage = [&](uint32_t st) {
        const int l7 = lane & 7, mt = lane >> 3;
        #pragma unroll
        for (int ks = 0; ks < 2; ks++) {
            uint32_t af_h[MT][4], af_l[MT][4];
            #pragma unroll
            for (int mi = 0; mi < MT; mi++) {
                uint32_t ra = st + (uint32_t)((wm + mi * 16 + l7 + ((mt & 1) << 3)) * ROWB
                                              + ks * 32 + ((mt >> 1) << 4));
                ldsm4(af_h[mi], ra);
                ldsm4(af_l[mi], ra + ATILE);
            }
            uint32_t bf_h[NT][2], bf_l[NT][2];
            #pragma unroll
            for (int np = 0; np < NT / 2; np++) {
                uint32_t rb = st + 2 * ATILE
                            + (uint32_t)((wn + np * 16 + ((mt >> 1) << 3) + l7) * ROWB
                                         + ks * 32 + ((mt & 1) << 4));
                uint32_t r4[4];
                ldsm4(r4, rb);
                bf_h[2 * np][0] = r4[0]; bf_h[2 * np][1] = r4[1];
                bf_h[2 * np + 1][0] = r4[2]; bf_h[2 * np + 1][1] = r4[3];
                ldsm4(r4, rb + BTILE);
                bf_l[2 * np][0] = r4[0]; bf_l[2 * np][1] = r4[1];
                bf_l[2 * np + 1][0] = r4[2]; bf_l[2 * np + 1][1] = r4[3];
            }
            #pragma unroll
            for (int mi = 0; mi < MT; mi++)
                #pragma unroll
                for (int ni = 0; ni < NT; ni++) {
                    mma_f16(acc[mi][ni], af_h[mi], bf_h[ni]);      // hi*hi -> fp32
                    mma_f16a(acc16[mi][ni], af_h[mi], bf_l[ni]);   // hi*lo -> fp16
                    mma_f16a(acc16[mi][ni], af_l[mi], bf_h[ni]);   // lo*hi -> fp16
                }
        }
    };

    cp_chunk(sb0, 0);
    CP_COMMIT();
    if (NC > 1) cp_chunk(sb0 + STAGE, 32);
    CP_COMMIT();
    for (int c = 0; c < NC; c++) {
        CP_WAIT1();
        __syncthreads();
        mma_stage(sb0 + (uint32_t)((c % 3) * STAGE));
        // 3-stage: cp(c+2) writes buffer (c-1)%3 whose readers passed the
        // barrier at the top of iter c — no second barrier needed.
        if (c + 2 < NC) cp_chunk(sb0 + (uint32_t)(((c + 2) % 3) * STAGE), (c + 2) * 32);
        CP_COMMIT();
    }

    // epilogue: fold fp16 cross-term accumulators into fp32, add bias, store
    const int g = lane >> 2, w2 = (lane & 3) * 2;
    #pragma unroll
    for (int ni = 0; ni < NT; ni++) {
        const int col = n0 + wn + ni * 8 + w2;
        float b0v = 0.f, b1v = 0.f;
        if (BMODE == 1) {
            const float* bp = (col < 256) ? Bi0 : (Bi1 - 256);
            b0v = bp[col]; b1v = bp[col + 1];
        } else if (BMODE == 2) {
            const float* bp = (col < 256) ? Bi0 : (col < 512 ? (Bi1 - 256) : (Bi2 - 512));
            b0v = bp[col]; b1v = bp[col + 1];
        }
        #pragma unroll
        for (int mi = 0; mi < MT; mi++) {
            const int row = m0 + wm + mi * 16 + g;
            __half2 x0 = *reinterpret_cast<__half2*>(&acc16[mi][ni][0]);
            __half2 x1 = *reinterpret_cast<__half2*>(&acc16[mi][ni][1]);
            float c00 = acc[mi][ni][0] + __low2float(x0) + b0v;
            float c01 = acc[mi][ni][1] + __high2float(x0) + b1v;
            float c10 = acc[mi][ni][2] + __low2float(x1) + b0v;
            float c11 = acc[mi][ni][3] + __high2float(x1) + b1v;
            if (OUT == 0 || OUT == 2) {
                *reinterpret_cast<float2*>(&C[(size_t)row * ldc + col]) = make_float2(c00, c01);
                *reinterpret_cast<float2*>(&C[(size_t)(row + 8) * ldc + col]) = make_float2(c10, c11);
            }
            if (OUT >= 1) {
                __half h0, l0, h1, l1;
                split1(c00, h0, l0); split1(c01, h1, l1);
                *reinterpret_cast<__half2*>(&Ch[(size_t)row * ldc + col]) = __halves2half2(h0, h1);
                *reinterpret_cast<__half2*>(&Cl[(size_t)row * ldc + col]) = __halves2half2(l0, l1);
                split1(c10, h0, l0); split1(c11, h1, l1);
                *reinterpret_cast<__half2*>(&Ch[(size_t)(row + 8) * ldc + col]) = __halves2half2(h0, h1);
                *reinterpret_cast<__half2*>(&Cl[(size_t)(row + 8) * ldc + col]) = __halves2half2(l0, l1);
            }
        }
    }
}

// unified config: 128x64 tile, 256 thr (8 warps, warp 32x32), 3-stage, 2 CTAs/SM
#define SMEMP  (3 * (2 * 128 * ROWB + 2 * 64 * ROWB))       // 92160

// ---------------- converts ----------------
template <bool STRAIGHT>
__global__ void cvt_split_T(const float* __restrict__ in, int ldin,
                            __half* __restrict__ oh, __half* __restrict__ ol,
                            __half* __restrict__ sh, __half* __restrict__ sl,
                            int R, int C)
{
    __shared__ float tile[32][33];
    const int c0 = blockIdx.x * 32, r0 = blockIdx.y * 32;
    const int tx = threadIdx.x, ty = threadIdx.y;
    #pragma unroll
    for (int i = 0; i < 32; i += 8) {
        float v = in[(size_t)(r0 + ty + i) * ldin + c0 + tx];
        tile[ty + i][tx] = v;
        if (STRAIGHT) {
            __half h, l;
            split1(v, h, l);
            const size_t o = (size_t)(r0 + ty + i) * C + c0 + tx;
            sh[o] = h;
            sl[o] = l;
        }
    }
    __syncthreads();
    #pragma unroll
    for (int i = 0; i < 32; i += 8) {
        float v = tile[tx][ty + i];
        __half h, l;
        split1(v, h, l);
        const size_t o = (size_t)(c0 + ty + i) * R + r0 + tx;
        oh[o] = h;
        ol[o] = l;
    }
}

__global__ void cvt_T_pair(const float* __restrict__ A, const float* __restrict__ B,
                           __half* __restrict__ oh, __half* __restrict__ ol,
                           int R, int C)
{
    __shared__ float tile[32][33];
    const int z = blockIdx.z;
    const float* in = z ? B : A;
    const size_t zoff = (size_t)z * C * R;
    const int c0 = blockIdx.x * 32, r0 = blockIdx.y * 32;
    const int tx = threadIdx.x, ty = threadIdx.y;
    #pragma unroll
    for (int i = 0; i < 32; i += 8)
        tile[ty + i][tx] = in[(size_t)(r0 + ty + i) * C + c0 + tx];
    __syncthreads();
    #pragma unroll
    for (int i = 0; i < 32; i += 8) {
        float v = tile[tx][ty + i];
        __half h, l;
        split1(v, h, l);
        const size_t o = zoff + (size_t)(c0 + ty + i) * R + r0 + tx;
        oh[o] = h;
        ol[o] = l;
    }
}

// ---------------- register-resident softmax + fp16 split output ----------------
__global__ void softmax_cvt(const float* __restrict__ Sc, __half* __restrict__ Ph,
                            __half* __restrict__ Pl)
{
    const size_t base = (size_t)blockIdx.x * S;
    const int t = threadIdx.x, lane = t & 31, wid = t >> 5;
    __shared__ float red[8];

    float4 v0 = *reinterpret_cast<const float4*>(Sc + base + t * 4);
    float4 v1 = *reinterpret_cast<const float4*>(Sc + base + 1024 + t * 4);
    float m = fmaxf(fmaxf(fmaxf(v0.x, v0.y), fmaxf(v0.z, v0.w)),
                    fmaxf(fmaxf(v1.x, v1.y), fmaxf(v1.z, v1.w)));
    #pragma unroll
    for (int o = 16; o > 0; o >>= 1) m = fmaxf(m, __shfl_xor_sync(0xffffffffu, m, o));
    if (lane == 0) red[wid] = m;
    __syncthreads();
    m = red[0];
    #pragma unroll
    for (int i = 1; i < 8; i++) m = fmaxf(m, red[i]);
    __syncthreads();

    float e[8];
    e[0] = __expf(v0.x - m); e[1] = __expf(v0.y - m);
    e[2] = __expf(v0.z - m); e[3] = __expf(v0.w - m);
    e[4] = __expf(v1.x - m); e[5] = __expf(v1.y - m);
    e[6] = __expf(v1.z - m); e[7] = __expf(v1.w - m);
    float s = e[0] + e[1] + e[2] + e[3] + e[4] + e[5] + e[6] + e[7];
    #pragma unroll
    for (int o = 16; o > 0; o >>= 1) s += __shfl_xor_sync(0xffffffffu, s, o);
    if (lane == 0) red[wid] = s;
    __syncthreads();
    s = red[0];
    #pragma unroll
    for (int i = 1; i < 8; i++) s += red[i];
    const float inv = 1.0f / s;

    #pragma unroll
    for (int half = 0; half < 2; half++) {
        const size_t o = base + half * 1024 + t * 4;
        __half h0, l0, h1, l1, h2, l2, h3, l3;
        split1(e[half * 4 + 0] * inv, h0, l0);
        split1(e[half * 4 + 1] * inv, h1, l1);
        split1(e[half * 4 + 2] * inv, h2, l2);
        split1(e[half * 4 + 3] * inv, h3, l3);
        *reinterpret_cast<__half2*>(Ph + o)     = __halves2half2(h0, h1);
        *reinterpret_cast<__half2*>(Ph + o + 2) = __halves2half2(h2, h3);
        *reinterpret_cast<__half2*>(Pl + o)     = __halves2half2(l0, l1);
        *reinterpret_cast<__half2*>(Pl + o + 2) = __halves2half2(l2, l3);
    }
}

// ---------------- row-wise L2 normalize (strided) ----------------
__global__ void l2norm_rows(float* __restrict__ V, int ld, int cols)
{
    float* row = V + (size_t)blockIdx.x * ld;
    __shared__ float red[128];
    const int t = threadIdx.x;
    float s = 0.f;
    for (int c = t; c < cols; c += 128) { float v = row[c]; s += v * v; }
    red[t] = s; __syncthreads();
    for (int st = 64; st > 0; st >>= 1) { if (t < st) red[t] += red[t + st]; __syncthreads(); }
    const float inv = 1.0f / sqrtf(red[0]);
    for (int c = t; c < cols; c += 128) row[c] *= inv;
}

// ---------------- block-3 tail ----------------
__global__ void rowproj(const float* __restrict__ h, const float* __restrict__ W,
                        const float* __restrict__ b, float* __restrict__ out,
                        int Din, int Nout)
{
    const int n = threadIdx.x;
    if (n >= Nout) return;
    float s = b[n];
    for (int d = 0; d < Din; d++) s = fmaf(h[d], W[(size_t)d * Nout + n], s);
    out[n] = s;
}

__global__ void dotrow(const float* __restrict__ q, const float* __restrict__ Kmat,
                       int ld, float* __restrict__ srow, int Kd)
{
    const int j = blockIdx.x;
    const int t = threadIdx.x;
    float s = 0.f;
    for (int c = t; c < Kd; c += 32) s = fmaf(q[c], Kmat[(size_t)j * ld + c], s);
    #pragma unroll
    for (int o = 16; o > 0; o >>= 1) s += __shfl_down_sync(0xffffffffu, s, o);
    if (t == 0) srow[j] = s;
}

__global__ void zero_out(float* out) { out[threadIdx.x + blockIdx.x * 256] = 0.f; }

// fused softmax (redundant per block) + slice-AV with atomic reduce
__global__ void av_split(const float* __restrict__ srow, const float* __restrict__ V,
                         int ld, float* __restrict__ out)
{
    __shared__ float probs[S];
    __shared__ float red[8];
    const int t = threadIdx.x, lane = t & 31, wid = t >> 5;

    float v[8];
    #pragma unroll
    for (int i = 0; i < 8; i++) v[i] = srow[t + i * 256];
    float m = v[0];
    #pragma unroll
    for (int i = 1; i < 8; i++) m = fmaxf(m, v[i]);
    #pragma unroll
    for (int o = 16; o > 0; o >>= 1) m = fmaxf(m, __shfl_xor_sync(0xffffffffu, m, o));
    if (lane == 0) red[wid] = m;
    __syncthreads();
    m = red[0];
    #pragma unroll
    for (int i = 1; i < 8; i++) m = fmaxf(m, red[i]);
    __syncthreads();

    float s = 0.f;
    #pragma unroll
    for (int i = 0; i < 8; i++) {
        float e = __expf(v[i] - m);
        probs[t + i * 256] = e;
        s += e;
    }
    #pragma unroll
    for (int o = 16; o > 0; o >>= 1) s += __shfl_xor_sync(0xffffffffu, s, o);
    if (lane == 0) red[wid] = s;
    __syncthreads();
    s = red[0];
    #pragma unroll
    for (int i = 1; i < 8; i++) s += red[i];
    const float inv = 1.0f / s;
    __syncthreads();

    const int d = blockIdx.x * 256 + t;
    const int j0 = blockIdx.y * 128;
    float acc = 0.f;
    #pragma unroll 4
    for (int j = j0; j < j0 + 128; j++)
        acc = fmaf(probs[j], V[(size_t)j * ld + d], acc);
    atomicAdd(out + d, acc * inv);
}

// ---------------- launch ----------------
extern "C" void kernel_launch(void* const* d_in, const int* in_sizes, int n_in,
                              void* d_out, int out_size)
{
    const float* x   = (const float*)d_in[0];   // [8,S,D] — batch 0 only
    const float* Wk1 = (const float*)d_in[1];
    const float* bk1 = (const float*)d_in[2];
    const float* Wq1 = (const float*)d_in[3];
    const float* bq1 = (const float*)d_in[4];
    const float* Wk2 = (const float*)d_in[5];
    const float* bk2 = (const float*)d_in[6];
    const float* Wq2 = (const float*)d_in[7];
    const float* bq2 = (const float*)d_in[8];
    const float* Wv2 = (const float*)d_in[9];
    const float* bv2 = (const float*)d_in[10];
    float* out = (float*)d_out;

    float *sc, *qkv32, *h2, *qrow, *srow;
    cudaGetSymbolAddress((void**)&sc,    g_sc);
    cudaGetSymbolAddress((void**)&qkv32, g_qkv32);
    cudaGetSymbolAddress((void**)&h2,    g_h2);
    cudaGetSymbolAddress((void**)&qrow,  g_qrow);
    cudaGetSymbolAddress((void**)&srow,  g_srow);

    __half *xh, *xl, *xTh, *xTl, *wqk1h, *wqk1l, *wqkv2h, *wqkv2l;
    __half *qk1h, *qk1l, *qkvh, *qkvl, *ph, *pl, *h1h, *h1l, *vTh, *vTl, *h2h, *h2l;
    cudaGetSymbolAddress((void**)&xh, g_xh);   cudaGetSymbolAddress((void**)&xl, g_xl);
    cudaGetSymbolAddress((void**)&xTh, g_xTh); cudaGetSymbolAddress((void**)&xTl, g_xTl);
    cudaGetSymbolAddress((void**)&wqk1h, g_wqk1h);   cudaGetSymbolAddress((void**)&wqk1l, g_wqk1l);
    cudaGetSymbolAddress((void**)&wqkv2h, g_wqkv2h); cudaGetSymbolAddress((void**)&wqkv2l, g_wqkv2l);
    cudaGetSymbolAddress((void**)&qk1h, g_qk1h); cudaGetSymbolAddress((void**)&qk1l, g_qk1l);
    cudaGetSymbolAddress((void**)&qkvh, g_qkvh); cudaGetSymbolAddress((void**)&qkvl, g_qkvl);
    cudaGetSymbolAddress((void**)&ph, g_ph); cudaGetSymbolAddress((void**)&pl, g_pl);
    cudaGetSymbolAddress((void**)&h1h, g_h1h); cudaGetSymbolAddress((void**)&h1l, g_h1l);
    cudaGetSymbolAddress((void**)&vTh, g_vTh); cudaGetSymbolAddress((void**)&vTl, g_vTl);
    cudaGetSymbolAddress((void**)&h2h, g_h2h); cudaGetSymbolAddress((void**)&h2l, g_h2l);

    cudaFuncSetAttribute((const void*)mma_gemm<128, 64, 4, 2, 1, 1>,
                         cudaFuncAttributeMaxDynamicSharedMemorySize, SMEMP);
    cudaFuncSetAttribute((const void*)mma_gemm<128, 64, 4, 2, 1, 0>,
                         cudaFuncAttributeMaxDynamicSharedMemorySize, SMEMP);
    cudaFuncSetAttribute((const void*)mma_gemm<128, 64, 4, 2, 2, 2>,
                         cudaFuncAttributeMaxDynamicSharedMemorySize, SMEMP);
    cudaFuncSetAttribute((const void*)mma_gemm<128, 64, 4, 2, 2, 0>,
                         cudaFuncAttributeMaxDynamicSharedMemorySize, SMEMP);
    cudaFuncSetAttribute((const void*)mma_gemm<128, 64, 4, 2, 0, 2>,
                         cudaFuncAttributeMaxDynamicSharedMemorySize, SMEMP);
    cudaFuncSetAttribute((const void*)mma_gemm<128, 64, 4, 2, 0, 0>,
                         cudaFuncAttributeMaxDynamicSharedMemorySize, SMEMP);

    const dim3 gP1(512 / 64, S / 128);    // (8,16)
    const dim3 gP2(1024 / 64, S / 128);   // (16,16)
    const dim3 gScor(S / 64, S / 128);    // (32,16) = 512 CTAs
    const dim3 gAV(D / 64, S / 128);      // (8,16)
    const dim3 tT(32, 8);

    // ---------- Block 1 ----------
    cvt_split_T<true><<<dim3(D / 32, S / 32), tT>>>(x, D, xTh, xTl, xh, xl, S, D);
    cvt_T_pair<<<dim3(KC / 32, D / 32, 2), tT>>>(Wq1, Wk1, wqk1h, wqk1l, D, KC);
    mma_gemm<128, 64, 4, 2, 1, 1><<<gP1, 256, SMEMP>>>(xh, xl, wqk1h, wqk1l,
        bq1, bk1, nullptr, nullptr, qk1h, qk1l, D, D, D, 512);
    mma_gemm<128, 64, 4, 2, 0, 0><<<gScor, 256, SMEMP>>>(qk1h, qk1l, qk1h + 256, qk1l + 256,
        nullptr, nullptr, nullptr, sc, nullptr, nullptr, KC, 512, 512, S);
    softmax_cvt<<<S, 256>>>(sc, ph, pl);
    mma_gemm<128, 64, 4, 2, 1, 0><<<gAV, 256, SMEMP>>>(ph, pl, xTh, xTl,
        nullptr, nullptr, nullptr, nullptr, h1h, h1l, S, S, S, D);

    // ---------- Block 2 ----------
    cvt_T_pair<<<dim3(KC / 32, D / 32, 2), tT>>>(Wq2, Wk2, wqkv2h, wqkv2l, D, KC);
    cvt_split_T<false><<<dim3(D / 32, D / 32), tT>>>(Wv2, D, wqkv2h + 512 * D, wqkv2l + 512 * D,
        nullptr, nullptr, D, D);
    mma_gemm<128, 64, 4, 2, 2, 2><<<gP2, 256, SMEMP>>>(h1h, h1l, wqkv2h, wqkv2l,
        bq2, bk2, bv2, qkv32, qkvh, qkvl, D, D, D, 1024);
    l2norm_rows<<<S, 128>>>(qkv32 + 512, 1024, D);
    cvt_split_T<false><<<dim3(D / 32, S / 32), tT>>>(qkv32 + 512, 1024, vTh, vTl,
        nullptr, nullptr, S, D);
    mma_gemm<128, 64, 4, 2, 0, 0><<<gScor, 256, SMEMP>>>(qkvh, qkvl, qkvh + 256, qkvl + 256,
        nullptr, nullptr, nullptr, sc, nullptr, nullptr, KC, 1024, 1024, S);
    softmax_cvt<<<S, 256>>>(sc, ph, pl);
    mma_gemm<128, 64, 4, 2, 2, 0><<<gAV, 256, SMEMP>>>(ph, pl, vTh, vTl,
        nullptr, nullptr, nullptr, h2, h2h, h2l, S, S, S, D);

    // ---------- Block 3 (only last query row needed) ----------
    mma_gemm<128, 64, 4, 2, 0, 2><<<gP2, 256, SMEMP>>>(h2h, h2l, wqkv2h, wqkv2l,
        bq2, bk2, bv2, qkv32, nullptr, nullptr, D, D, D, 1024);
    l2norm_rows<<<S, 128>>>(qkv32 + 512, 1024, D);
    rowproj<<<1, KC>>>(h2 + (size_t)(S - 1) * D, Wq2, bq2, qrow, D, KC);
    dotrow<<<S, 32>>>(qrow, qkv32 + 256, 1024, srow, KC);
    zero_out<<<2, 256>>>(out);
    av_split<<<dim3(2, 16), 256>>>(srow, qkv32 + 512, 1024, out);
}